// round 1
// baseline (speedup 1.0000x reference)
#include <cuda_runtime.h>
#include <math.h>

#define NB      4
#define SEQ     1024
#define DMODEL  768
#define NH      12
#define DHD     64
#define J3      2304
#define MROWS   4096          // NB*SEQ
#define BHN     48            // NB*NH

// ---------------- scratch (device globals: allocation-free rule) ----------------
__device__ float    g_xq[MROWS*DMODEL];          // quantized x (reused for quantized out)
__device__ float    g_wq1[DMODEL*J3];            // quantized w_qkv^T
__device__ float    g_xqkv[MROWS*J3];            // qkv projection output
__device__ float    g_dots[(size_t)BHN*SEQ*SEQ]; // logits, then softmax a (in place)
__device__ float    g_outbuf[MROWS*DMODEL];      // attention output (b,n,h*64+d)
__device__ float    g_wq2[DMODEL*DMODEL];        // quantized w_out^T
__device__ float    g_rowsum_x[MROWS];
__device__ float    g_colsum_w1[J3];
__device__ float    g_xqkvsum[MROWS];
__device__ float    g_rowsumq[BHN*SEQ];
__device__ float    g_colsumk[BHN*SEQ];
__device__ float    g_vcolsum[BHN*DHD];
__device__ float    g_colsum_w2[DMODEL];
__device__ unsigned g_stat[16];                  // slot*2 = max(enc), slot*2+1 = min(enc)
// slots: 0=x 1=w1 2=q 3=k 4=v 5=a 6=out 7=w2

// ---------------- helpers ----------------
__device__ __forceinline__ unsigned fenc(float f){
    unsigned u = __float_as_uint(f);
    return (u & 0x80000000u) ? ~u : (u | 0x80000000u);
}
__device__ __forceinline__ float fdec(unsigned e){
    return (e & 0x80000000u) ? __uint_as_float(e ^ 0x80000000u) : __uint_as_float(~e);
}
// s = (max-min)/15, z = round(15 - max/s)  (exact IEEE ops to match jax f32)
__device__ __forceinline__ void get_sz(int slot, float& s, float& z){
    float mx = fdec(g_stat[2*slot]);
    float mn = fdec(g_stat[2*slot+1]);
    s = __fdiv_rn(mx - mn, 15.0f);
    z = rintf(15.0f - __fdiv_rn(mx, s));
}
__device__ __forceinline__ float quant(float v, float s, float z){
    return rintf(__fdiv_rn(v, s) + z);
}

// ---------------- kernels ----------------
__global__ void k_init(){
    int t = threadIdx.x;
    if (t < 8){ g_stat[2*t] = fenc(-INFINITY); g_stat[2*t+1] = fenc(INFINITY); }
}

__global__ void k_minmax(const float* __restrict__ p, int n, int slot){
    float mx = -INFINITY, mn = INFINITY;
    for (int i = blockIdx.x*blockDim.x + threadIdx.x; i < n; i += gridDim.x*blockDim.x){
        float v = p[i]; mx = fmaxf(mx, v); mn = fminf(mn, v);
    }
    __shared__ float smx[256], smn[256];
    int t = threadIdx.x;
    smx[t] = mx; smn[t] = mn; __syncthreads();
    for (int o = 128; o > 0; o >>= 1){
        if (t < o){ smx[t] = fmaxf(smx[t], smx[t+o]); smn[t] = fminf(smn[t], smn[t+o]); }
        __syncthreads();
    }
    if (t == 0){
        atomicMax(&g_stat[2*slot],   fenc(smx[0]));
        atomicMin(&g_stat[2*slot+1], fenc(smn[0]));
    }
}

// min/max of q,k,v regions of xqkv in one pass (slots 2,3,4)
__global__ void k_minmax3(){
    float mx[3] = {-INFINITY,-INFINITY,-INFINITY};
    float mn[3] = { INFINITY, INFINITY, INFINITY};
    const int n = MROWS*J3;
    for (int i = blockIdx.x*blockDim.x + threadIdx.x; i < n; i += gridDim.x*blockDim.x){
        int c = i % J3;
        int r = c / DMODEL;      // 0=q 1=k 2=v
        float v = g_xqkv[i];
        mx[r] = fmaxf(mx[r], v); mn[r] = fminf(mn[r], v);
    }
    __shared__ unsigned sm[6];
    if (threadIdx.x < 6) sm[threadIdx.x] = (threadIdx.x & 1) ? fenc(INFINITY) : fenc(-INFINITY);
    __syncthreads();
    for (int r = 0; r < 3; r++){
        atomicMax(&sm[2*r],   fenc(mx[r]));
        atomicMin(&sm[2*r+1], fenc(mn[r]));
    }
    __syncthreads();
    if (threadIdx.x < 3)                      atomicMax(&g_stat[2*(2+threadIdx.x)],       sm[2*threadIdx.x]);
    else if (threadIdx.x < 6){ int r = threadIdx.x-3; atomicMin(&g_stat[2*(2+r)+1], sm[2*r+1]); }
}

// quantize rows of src (rows = gridDim.x), write dst, fused row sums
__global__ void k_quantrow(const float* __restrict__ src, float* __restrict__ dst,
                           float* __restrict__ rowsum, int slot, int rowlen){
    int r = blockIdx.x;
    float s, z; get_sz(slot, s, z);
    float acc = 0.f;
    for (int c = threadIdx.x; c < rowlen; c += blockDim.x){
        float v = quant(src[(size_t)r*rowlen + c], s, z);
        dst[(size_t)r*rowlen + c] = v;
        acc += v;
    }
    __shared__ float sh[256];
    sh[threadIdx.x] = acc; __syncthreads();
    for (int o = 128; o > 0; o >>= 1){ if (threadIdx.x < o) sh[threadIdx.x] += sh[threadIdx.x+o]; __syncthreads(); }
    if (threadIdx.x == 0) rowsum[r] = sh[0];
}

// quantize weight [Ncols][K] (torch layout) into transposed wq [K][Ncols], fused col sums
__global__ void k_quantW(const float* __restrict__ w, float* __restrict__ wq,
                         float* __restrict__ colsum, int slot, int K, int Ncols){
    int j = blockIdx.x;
    float s, z; get_sz(slot, s, z);
    float acc = 0.f;
    for (int d = threadIdx.x; d < K; d += blockDim.x){
        float v = quant(w[(size_t)j*K + d], s, z);
        wq[(size_t)d*Ncols + j] = v;
        acc += v;
    }
    __shared__ float sh[256];
    sh[threadIdx.x] = acc; __syncthreads();
    for (int o = 128; o > 0; o >>= 1){ if (threadIdx.x < o) sh[threadIdx.x] += sh[threadIdx.x+o]; __syncthreads(); }
    if (threadIdx.x == 0) colsum[j] = sh[0];
}

__global__ void k_rowsum(const float* __restrict__ src, float* __restrict__ out, int rowlen){
    int r = blockIdx.x;
    float acc = 0.f;
    for (int c = threadIdx.x; c < rowlen; c += blockDim.x) acc += src[(size_t)r*rowlen + c];
    __shared__ float sh[256];
    sh[threadIdx.x] = acc; __syncthreads();
    for (int o = 128; o > 0; o >>= 1){ if (threadIdx.x < o) sh[threadIdx.x] += sh[threadIdx.x+o]; __syncthreads(); }
    if (threadIdx.x == 0) out[r] = sh[0];
}

// Tiled GEMM on quantized operands with affine correction epilogue.
// C[i][j] = (sum_k A[i][k]*B[k][j] - colsumB[j]*zA - rowsumV[i]*zB + zA*zB*Kconst)*(sA*sB) [+ bias[j]]
__global__ void k_gemm(const float* __restrict__ A, const float* __restrict__ Bm, float* __restrict__ C,
                       int M, int Nc, int K,
                       const float* __restrict__ colsumB, const float* __restrict__ rowsumV,
                       int slotA, int slotB, float Kconst, const float* __restrict__ bias){
    float sA, zA, sB, zB;
    get_sz(slotA, sA, zA); get_sz(slotB, sB, zB);
    float mult  = sA * sB;
    float cterm = (zA * zB) * Kconst;

    __shared__ float As[16][65];  // [k][i]
    __shared__ float Bs[16][64];  // [k][j]
    int tid = threadIdx.x;
    int tx = tid % 16, ty = tid / 16;
    int i0 = blockIdx.y * 64, j0 = blockIdx.x * 64;
    float acc[4][4] = {};

    for (int k0 = 0; k0 < K; k0 += 16){
        for (int l = tid; l < 1024; l += 256){
            int r = l >> 4, c = l & 15;
            As[c][r] = A[(size_t)(i0 + r)*K + k0 + c];
        }
        for (int l = tid; l < 1024; l += 256){
            int r = l >> 6, c = l & 63;
            Bs[r][c] = Bm[(size_t)(k0 + r)*Nc + j0 + c];
        }
        __syncthreads();
        #pragma unroll
        for (int k = 0; k < 16; k++){
            float ar[4], br[4];
            #pragma unroll
            for (int a = 0; a < 4; a++){ ar[a] = As[k][ty*4 + a]; br[a] = Bs[k][tx*4 + a]; }
            #pragma unroll
            for (int a = 0; a < 4; a++)
                #pragma unroll
                for (int b = 0; b < 4; b++) acc[a][b] += ar[a]*br[b];
        }
        __syncthreads();
    }
    #pragma unroll
    for (int a = 0; a < 4; a++){
        int gi = i0 + ty*4 + a;
        #pragma unroll
        for (int b = 0; b < 4; b++){
            int gj = j0 + tx*4 + b;
            float v = (acc[a][b] - colsumB[gj]*zA - rowsumV[gi]*zB + cterm) * mult;
            if (bias) v += bias[gj];
            C[(size_t)gi*Nc + gj] = v;
        }
    }
}

// per-(b,h,token): sum_d qq and sum_d kq
__global__ void k_sumqk(){
    int n = blockIdx.x, bh = blockIdx.y;
    int b = bh / NH, h = bh - b*NH;
    float sq, zq, sk, zk;
    get_sz(2, sq, zq); get_sz(3, sk, zk);
    int base = (b*SEQ + n)*J3 + h*DHD;
    int t = threadIdx.x; // 64
    float qv = quant(g_xqkv[base + t],          sq, zq);
    float kv = quant(g_xqkv[base + DMODEL + t], sk, zk);
    __shared__ float sA[64], sB[64];
    sA[t] = qv; sB[t] = kv; __syncthreads();
    for (int o = 32; o > 0; o >>= 1){
        if (t < o){ sA[t] += sA[t+o]; sB[t] += sB[t+o]; }
        __syncthreads();
    }
    if (t == 0){ g_rowsumq[bh*SEQ + n] = sA[0]; g_colsumk[bh*SEQ + n] = sB[0]; }
}

// dots[b,h,i,j] = (sum_d qq*kq - colsumk[j]*zq - rowsumq[i]*zk) * (scale*sq*sk)
__global__ void k_dots(){
    int jt = blockIdx.x, it = blockIdx.y, bh = blockIdx.z;
    int b = bh / NH, h = bh - b*NH;
    float sq, zq, sk, zk;
    get_sz(2, sq, zq); get_sz(3, sk, zk);
    float s3 = (0.125f * sq) * sk;

    __shared__ float Qs[64][65], Ks[64][65];
    int tid = threadIdx.x;
    for (int l = tid; l < 64*64; l += 256){
        int r = l >> 6, c = l & 63;
        Qs[r][c] = quant(g_xqkv[(size_t)(b*SEQ + it*64 + r)*J3 + h*DHD + c],          sq, zq);
        Ks[r][c] = quant(g_xqkv[(size_t)(b*SEQ + jt*64 + r)*J3 + DMODEL + h*DHD + c], sk, zk);
    }
    __syncthreads();
    int tx = tid % 16, ty = tid / 16;
    int ty4 = ty*4, tx4 = tx*4;
    float acc[4][4] = {};
    #pragma unroll 4
    for (int d = 0; d < 64; d++){
        float ar[4], br[4];
        #pragma unroll
        for (int a = 0; a < 4; a++){ ar[a] = Qs[ty4+a][d]; br[a] = Ks[tx4+a][d]; }
        #pragma unroll
        for (int a = 0; a < 4; a++)
            #pragma unroll
            for (int bb = 0; bb < 4; bb++) acc[a][bb] += ar[a]*br[bb];
    }
    #pragma unroll
    for (int a = 0; a < 4; a++){
        int gi = it*64 + ty4 + a;
        #pragma unroll
        for (int bb = 0; bb < 4; bb++){
            int gj = jt*64 + tx4 + bb;
            float v = (acc[a][bb] - g_colsumk[bh*SEQ + gj]*zq - g_rowsumq[bh*SEQ + gi]*zk) * s3;
            g_dots[((size_t)bh*SEQ + gi)*SEQ + gj] = v;
        }
    }
}

// in-place softmax per row; also harvest global min/max of a (slot 5)
__global__ void k_softmax(){
    int i = blockIdx.x, bh = blockIdx.y;
    float* row = g_dots + ((size_t)bh*SEQ + i)*SEQ;
    __shared__ float red[256];
    __shared__ float buf[1024];
    int t = threadIdx.x;
    float mx = -INFINITY;
    for (int j = t; j < SEQ; j += 256){ float v = row[j]; buf[j] = v; mx = fmaxf(mx, v); }
    red[t] = mx; __syncthreads();
    for (int o = 128; o > 0; o >>= 1){ if (t < o) red[t] = fmaxf(red[t], red[t+o]); __syncthreads(); }
    float m = red[0]; __syncthreads();
    float sum = 0.f;
    for (int j = t; j < SEQ; j += 256){ float e = expf(buf[j] - m); buf[j] = e; sum += e; }
    red[t] = sum; __syncthreads();
    for (int o = 128; o > 0; o >>= 1){ if (t < o) red[t] += red[t+o]; __syncthreads(); }
    float S = red[0]; __syncthreads();
    float lmx = -INFINITY, lmn = INFINITY;
    for (int j = t; j < SEQ; j += 256){
        float a = __fdiv_rn(buf[j], S);
        row[j] = a;
        lmx = fmaxf(lmx, a); lmn = fminf(lmn, a);
    }
    red[t] = lmx; __syncthreads();
    for (int o = 128; o > 0; o >>= 1){ if (t < o) red[t] = fmaxf(red[t], red[t+o]); __syncthreads(); }
    float gm = red[0]; __syncthreads();
    red[t] = lmn; __syncthreads();
    for (int o = 128; o > 0; o >>= 1){ if (t < o) red[t] = fminf(red[t], red[t+o]); __syncthreads(); }
    if (t == 0){
        atomicMax(&g_stat[10], fenc(gm));
        atomicMin(&g_stat[11], fenc(red[0]));
    }
}

// vq.sum over tokens per (b,h,d)
__global__ void k_vcolsum(){
    int bh = blockIdx.x;
    int b = bh / NH, h = bh - b*NH;
    float sv, zv; get_sz(4, sv, zv);
    int d = threadIdx.x; // 64
    float acc = 0.f;
    for (int n = 0; n < SEQ; n++)
        acc += quant(g_xqkv[(size_t)(b*SEQ + n)*J3 + 2*DMODEL + h*DHD + d], sv, zv);
    g_vcolsum[bh*DHD + d] = acc;
}

// out[b,h,i,d] = (sum_j aq*vq - vcolsum[d]*za - rowsum_aq[i]*zv + za*zv*SEQ)*(sa*sv)
__global__ void k_av(){
    int it = blockIdx.x, bh = blockIdx.y;
    int b = bh / NH, h = bh - b*NH;
    float sa, za, sv, zv;
    get_sz(5, sa, za); get_sz(4, sv, zv);

    __shared__ float As[64][65], Vs[64][65];
    __shared__ float rsum[64];
    int tid = threadIdx.x;
    int tx = tid % 16, ty = tid / 16;
    int ty4 = ty*4, tx4 = tx*4;
    float acc[4][4] = {};
    float myrs = 0.f;

    for (int jt = 0; jt < 16; jt++){
        for (int l = tid; l < 64*64; l += 256){
            int r = l >> 6, c = l & 63;
            As[r][c] = quant(g_dots[((size_t)bh*SEQ + it*64 + r)*SEQ + jt*64 + c], sa, za);
            Vs[r][c] = quant(g_xqkv[(size_t)(b*SEQ + jt*64 + r)*J3 + 2*DMODEL + h*DHD + c], sv, zv);
        }
        __syncthreads();
        if (tid < 64){
            float s = 0.f;
            #pragma unroll 8
            for (int c = 0; c < 64; c++) s += As[tid][c];
            myrs += s;
        }
        #pragma unroll 4
        for (int jj = 0; jj < 64; jj++){
            float ar[4], vr[4];
            #pragma unroll
            for (int a = 0; a < 4; a++){ ar[a] = As[ty4+a][jj]; vr[a] = Vs[jj][tx4+a]; }
            #pragma unroll
            for (int a = 0; a < 4; a++)
                #pragma unroll
                for (int bb = 0; bb < 4; bb++) acc[a][bb] += ar[a]*vr[bb];
        }
        __syncthreads();
    }
    if (tid < 64) rsum[tid] = myrs;
    __syncthreads();

    float mult  = sa * sv;
    float cterm = (za * zv) * (float)SEQ;
    #pragma unroll
    for (int a = 0; a < 4; a++){
        int li = ty4 + a;
        #pragma unroll
        for (int bb = 0; bb < 4; bb++){
            int d = tx4 + bb;
            float v = (acc[a][bb] - g_vcolsum[bh*DHD + d]*za - rsum[li]*zv + cterm) * mult;
            g_outbuf[(size_t)(b*SEQ + it*64 + li)*DMODEL + h*DHD + d] = v;
        }
    }
}

// ---------------- launcher ----------------
extern "C" void kernel_launch(void* const* d_in, const int* in_sizes, int n_in,
                              void* d_out, int out_size){
    const float *x = nullptr, *wqkv = nullptr, *wout = nullptr, *bout = nullptr;
    for (int i = 0; i < n_in; i++){
        if      (in_sizes[i] == MROWS*DMODEL)  x    = (const float*)d_in[i];
        else if (in_sizes[i] == J3*DMODEL)     wqkv = (const float*)d_in[i];
        else if (in_sizes[i] == DMODEL*DMODEL) wout = (const float*)d_in[i];
        else if (in_sizes[i] == DMODEL)        bout = (const float*)d_in[i];
    }
    float* out = (float*)d_out;

    float *p_xq, *p_wq1, *p_xqkv, *p_outbuf, *p_wq2;
    float *p_rowsum_x, *p_colsum_w1, *p_xqkvsum, *p_colsum_w2;
    cudaGetSymbolAddress((void**)&p_xq,        g_xq);
    cudaGetSymbolAddress((void**)&p_wq1,       g_wq1);
    cudaGetSymbolAddress((void**)&p_xqkv,      g_xqkv);
    cudaGetSymbolAddress((void**)&p_outbuf,    g_outbuf);
    cudaGetSymbolAddress((void**)&p_wq2,       g_wq2);
    cudaGetSymbolAddress((void**)&p_rowsum_x,  g_rowsum_x);
    cudaGetSymbolAddress((void**)&p_colsum_w1, g_colsum_w1);
    cudaGetSymbolAddress((void**)&p_xqkvsum,   g_xqkvsum);
    cudaGetSymbolAddress((void**)&p_colsum_w2, g_colsum_w2);

    k_init<<<1, 32>>>();
    k_minmax<<<1024, 256>>>(x,    MROWS*DMODEL, 0);
    k_minmax<<<1024, 256>>>(wqkv, J3*DMODEL,    1);
    k_quantrow<<<MROWS, 256>>>(x, p_xq, p_rowsum_x, 0, DMODEL);
    k_quantW<<<J3, 256>>>(wqkv, p_wq1, p_colsum_w1, 1, DMODEL, J3);
    k_gemm<<<dim3(J3/64, MROWS/64), 256>>>(p_xq, p_wq1, p_xqkv, MROWS, J3, DMODEL,
                                           p_colsum_w1, p_rowsum_x, 0, 1,
                                           (float)DMODEL, nullptr);
    k_rowsum<<<MROWS, 256>>>(p_xqkv, p_xqkvsum, J3);
    k_minmax3<<<2048, 256>>>();
    k_sumqk<<<dim3(SEQ, BHN), 64>>>();
    k_dots<<<dim3(16, 16, BHN), 256>>>();
    k_softmax<<<dim3(SEQ, BHN), 256>>>();
    k_vcolsum<<<BHN, 64>>>();
    k_av<<<dim3(16, BHN), 256>>>();
    k_minmax<<<1024, 256>>>(p_outbuf, MROWS*DMODEL,  6);
    k_minmax<<<1024, 256>>>(wout,     DMODEL*DMODEL, 7);
    k_quantrow<<<MROWS, 256>>>(p_outbuf, p_xq, p_rowsum_x /*dummy*/, 6, DMODEL);
    k_quantW<<<DMODEL, 256>>>(wout, p_wq2, p_colsum_w2, 7, DMODEL, DMODEL);
    k_gemm<<<dim3(DMODEL/64, MROWS/64), 256>>>(p_xq, p_wq2, out, MROWS, DMODEL, DMODEL,
                                               p_colsum_w2, p_xqkvsum, 6, 7,
                                               (float)J3, bout);
}

// round 4
// speedup vs baseline: 3.5703x; 3.5703x over previous
#include <cuda_runtime.h>
#include <cuda_bf16.h>
#include <cstdint>
#include <cstddef>
#include <math.h>

#define NB      4
#define SEQ     1024
#define DMODEL  768
#define NH      12
#define DHD     64
#define J3      2304
#define MROWS   4096          // NB*SEQ
#define BHN     48            // NB*NH

typedef __nv_bfloat16 bf16;
typedef unsigned int  u32;

// ---------------- scratch ----------------
__device__ __align__(16) bf16  g_xq[MROWS*DMODEL];          // quantized x / quantized attn-out (bf16)
__device__ __align__(16) bf16  g_wq1[DMODEL*J3];            // quantized w_qkv^T  [k][n]
__device__ __align__(16) bf16  g_wq2[DMODEL*DMODEL];        // quantized w_out^T  [k][n]
__device__ __align__(16) float g_xqkv[MROWS*J3];            // qkv projection output (f32)
__device__ __align__(16) bf16  g_qb[BHN*SEQ*DHD];           // packed quantized q
__device__ __align__(16) bf16  g_kb[BHN*SEQ*DHD];           // packed quantized k
__device__ __align__(16) bf16  g_vb[BHN*SEQ*DHD];           // packed quantized v
__device__ __align__(16) float g_dots[(long long)BHN*SEQ*SEQ]; // logits -> softmax a (in place)
__device__ __align__(16) bf16  g_aqb[(long long)BHN*SEQ*SEQ];  // quantized a (bf16)
__device__ __align__(16) float g_outbuf[MROWS*DMODEL];      // attention output (b,n,h*64+d)
__device__ float    g_rowsum_x[MROWS];
__device__ float    g_colsum_w1[J3];
__device__ float    g_colsum_w2[DMODEL];
__device__ float    g_xqkvsum[MROWS];
__device__ float    g_rowsumq[BHN*SEQ];
__device__ float    g_colsumk[BHN*SEQ];
__device__ float    g_vcolsum[BHN*DHD];
__device__ float    g_aqrowsum[BHN*SEQ];
__device__ unsigned g_stat[16];   // slot*2=max(enc), slot*2+1=min(enc). slots:0=x 1=w1 2=q 3=k 4=v 5=a 6=out 7=w2

// ---------------- helpers ----------------
__device__ __forceinline__ unsigned fenc(float f){
    unsigned u = __float_as_uint(f);
    return (u & 0x80000000u) ? ~u : (u | 0x80000000u);
}
__device__ __forceinline__ float fdec(unsigned e){
    return (e & 0x80000000u) ? __uint_as_float(e ^ 0x80000000u) : __uint_as_float(~e);
}
__device__ __forceinline__ void get_sz(int slot, float& s, float& z){
    float mx = fdec(g_stat[2*slot]);
    float mn = fdec(g_stat[2*slot+1]);
    s = __fdiv_rn(mx - mn, 15.0f);
    z = rintf(15.0f - __fdiv_rn(mx, s));
}
__device__ __forceinline__ float quant(float v, float s, float z){
    return rintf(__fdiv_rn(v, s) + z);
}

__device__ __forceinline__ void ldsm4(u32* r, const void* p){
    u32 a = (u32)__cvta_generic_to_shared(p);
    asm volatile("ldmatrix.sync.aligned.m8n8.x4.shared.b16 {%0,%1,%2,%3},[%4];"
        : "=r"(r[0]),"=r"(r[1]),"=r"(r[2]),"=r"(r[3]) : "r"(a));
}
__device__ __forceinline__ void ldsm2(u32* r, const void* p){
    u32 a = (u32)__cvta_generic_to_shared(p);
    asm volatile("ldmatrix.sync.aligned.m8n8.x2.shared.b16 {%0,%1},[%2];"
        : "=r"(r[0]),"=r"(r[1]) : "r"(a));
}
__device__ __forceinline__ void ldsm2t(u32* r, const void* p){
    u32 a = (u32)__cvta_generic_to_shared(p);
    asm volatile("ldmatrix.sync.aligned.m8n8.x2.trans.shared.b16 {%0,%1},[%2];"
        : "=r"(r[0]),"=r"(r[1]) : "r"(a));
}
__device__ __forceinline__ void mma16816(float* c, const u32* a, const u32* b){
    asm volatile("mma.sync.aligned.m16n8k16.row.col.f32.bf16.bf16.f32 "
        "{%0,%1,%2,%3}, {%4,%5,%6,%7}, {%8,%9}, {%0,%1,%2,%3};"
        : "+f"(c[0]),"+f"(c[1]),"+f"(c[2]),"+f"(c[3])
        : "r"(a[0]),"r"(a[1]),"r"(a[2]),"r"(a[3]), "r"(b[0]),"r"(b[1]));
}

// ---------------- elementwise kernels ----------------
__global__ void k_init(){
    int t = threadIdx.x;
    if (t < 8){ g_stat[2*t] = fenc(-INFINITY); g_stat[2*t+1] = fenc(INFINITY); }
    for (int i = t; i < BHN*DHD; i += blockDim.x) g_vcolsum[i] = 0.f;
}

__global__ void k_minmax(const float* __restrict__ p, int n, int slot){
    float mx = -INFINITY, mn = INFINITY;
    for (int i = blockIdx.x*blockDim.x + threadIdx.x; i < n; i += gridDim.x*blockDim.x){
        float v = p[i]; mx = fmaxf(mx, v); mn = fminf(mn, v);
    }
    __shared__ float smx[256], smn[256];
    int t = threadIdx.x;
    smx[t] = mx; smn[t] = mn; __syncthreads();
    for (int o = 128; o > 0; o >>= 1){
        if (t < o){ smx[t] = fmaxf(smx[t], smx[t+o]); smn[t] = fminf(smn[t], smn[t+o]); }
        __syncthreads();
    }
    if (t == 0){
        atomicMax(&g_stat[2*slot],   fenc(smx[0]));
        atomicMin(&g_stat[2*slot+1], fenc(smn[0]));
    }
}

__global__ void k_minmax3(){
    float mx0=-INFINITY, mx1=-INFINITY, mx2=-INFINITY;
    float mn0= INFINITY, mn1= INFINITY, mn2= INFINITY;
    const int n = MROWS*J3;
    for (int i = blockIdx.x*blockDim.x + threadIdx.x; i < n; i += gridDim.x*blockDim.x){
        int c = i % J3;
        int r = c / DMODEL;
        float v = g_xqkv[i];
        if (r == 0){ mx0 = fmaxf(mx0, v); mn0 = fminf(mn0, v); }
        else if (r == 1){ mx1 = fmaxf(mx1, v); mn1 = fminf(mn1, v); }
        else { mx2 = fmaxf(mx2, v); mn2 = fminf(mn2, v); }
    }
    __shared__ unsigned sm[6];
    if (threadIdx.x < 6) sm[threadIdx.x] = (threadIdx.x & 1) ? fenc(INFINITY) : fenc(-INFINITY);
    __syncthreads();
    atomicMax(&sm[0], fenc(mx0)); atomicMin(&sm[1], fenc(mn0));
    atomicMax(&sm[2], fenc(mx1)); atomicMin(&sm[3], fenc(mn1));
    atomicMax(&sm[4], fenc(mx2)); atomicMin(&sm[5], fenc(mn2));
    __syncthreads();
    if (threadIdx.x < 3)       atomicMax(&g_stat[2*(2+threadIdx.x)],   sm[2*threadIdx.x]);
    else if (threadIdx.x < 6){ int r = threadIdx.x-3; atomicMin(&g_stat[2*(2+r)+1], sm[2*r+1]); }
}

// quantize rows -> bf16, fused row sums
__global__ void k_quantrow(const float* __restrict__ src, bf16* __restrict__ dst,
                           float* __restrict__ rowsum, int slot, int rowlen){
    int r = blockIdx.x;
    float s, z; get_sz(slot, s, z);
    float acc = 0.f;
    for (int c = threadIdx.x; c < rowlen; c += blockDim.x){
        float v = quant(src[(long long)r*rowlen + c], s, z);
        dst[(long long)r*rowlen + c] = __float2bfloat16(v);
        acc += v;
    }
    __shared__ float sh[256];
    sh[threadIdx.x] = acc; __syncthreads();
    for (int o = 128; o > 0; o >>= 1){ if (threadIdx.x < o) sh[threadIdx.x] += sh[threadIdx.x+o]; __syncthreads(); }
    if (threadIdx.x == 0) rowsum[r] = sh[0];
}

// quantize weight [Ncols][K] into transposed bf16 wq [K][Ncols], fused col sums
__global__ void k_quantW(const float* __restrict__ w, bf16* __restrict__ wq,
                         float* __restrict__ colsum, int slot, int K, int Ncols){
    int j = blockIdx.x;
    float s, z; get_sz(slot, s, z);
    float acc = 0.f;
    for (int d = threadIdx.x; d < K; d += blockDim.x){
        float v = quant(w[(long long)j*K + d], s, z);
        wq[(long long)d*Ncols + j] = __float2bfloat16(v);
        acc += v;
    }
    __shared__ float sh[256];
    sh[threadIdx.x] = acc; __syncthreads();
    for (int o = 128; o > 0; o >>= 1){ if (threadIdx.x < o) sh[threadIdx.x] += sh[threadIdx.x+o]; __syncthreads(); }
    if (threadIdx.x == 0) colsum[j] = sh[0];
}

__global__ void k_rowsum(const float* __restrict__ src, float* __restrict__ out, int rowlen){
    int r = blockIdx.x;
    float acc = 0.f;
    for (int c = threadIdx.x; c < rowlen; c += blockDim.x) acc += src[(long long)r*rowlen + c];
    __shared__ float sh[256];
    sh[threadIdx.x] = acc; __syncthreads();
    for (int o = 128; o > 0; o >>= 1){ if (threadIdx.x < o) sh[threadIdx.x] += sh[threadIdx.x+o]; __syncthreads(); }
    if (threadIdx.x == 0) out[r] = sh[0];
}

// pack quantized q/k/v into head-contiguous bf16 buffers; fused token-sums + v colsum atomics
__global__ void k_pack_qkv(){
    int bh = blockIdx.y;
    int b = bh / NH, h = bh - b*NH;
    int t = threadIdx.x;           // 256 = 4 tokens x 64 d
    int dtok = t >> 6, d = t & 63;
    int n = blockIdx.x*4 + dtok;
    float sq, zq, sk, zk, sv, zv;
    get_sz(2, sq, zq); get_sz(3, sk, zk); get_sz(4, sv, zv);
    long long base = (long long)(b*SEQ + n)*J3 + h*DHD + d;
    float qv = quant(g_xqkv[base],            sq, zq);
    float kv = quant(g_xqkv[base + DMODEL],   sk, zk);
    float vv = quant(g_xqkv[base + 2*DMODEL], sv, zv);
    long long po = ((long long)bh*SEQ + n)*DHD + d;
    g_qb[po] = __float2bfloat16(qv);
    g_kb[po] = __float2bfloat16(kv);
    g_vb[po] = __float2bfloat16(vv);
    __shared__ float shq[256], shk[256], shv[256];
    shq[t] = qv; shk[t] = kv; shv[t] = vv; __syncthreads();
    for (int o = 32; o > 0; o >>= 1){
        if (d < o){ shq[t] += shq[t+o]; shk[t] += shk[t+o]; }
        __syncthreads();
    }
    if (d == 0){
        g_rowsumq[bh*SEQ + n] = shq[t];
        g_colsumk[bh*SEQ + n] = shk[t];
    }
    if (t < 64){
        float s = shv[t] + shv[t+64] + shv[t+128] + shv[t+192];
        atomicAdd(&g_vcolsum[bh*DHD + t], s);
    }
}

// in-place softmax per row; harvest global min/max of a (slot 5)
__global__ void k_softmax(){
    int i = blockIdx.x, bh = blockIdx.y;
    float* row = g_dots + ((long long)bh*SEQ + i)*SEQ;
    __shared__ float red[256];
    __shared__ float buf[1024];
    int t = threadIdx.x;
    float mx = -INFINITY;
    for (int j = t; j < SEQ; j += 256){ float v = row[j]; buf[j] = v; mx = fmaxf(mx, v); }
    red[t] = mx; __syncthreads();
    for (int o = 128; o > 0; o >>= 1){ if (t < o) red[t] = fmaxf(red[t], red[t+o]); __syncthreads(); }
    float m = red[0]; __syncthreads();
    float sum = 0.f;
    for (int j = t; j < SEQ; j += 256){ float e = expf(buf[j] - m); buf[j] = e; sum += e; }
    red[t] = sum; __syncthreads();
    for (int o = 128; o > 0; o >>= 1){ if (t < o) red[t] += red[t+o]; __syncthreads(); }
    float S = red[0]; __syncthreads();
    float lmx = -INFINITY, lmn = INFINITY;
    for (int j = t; j < SEQ; j += 256){
        float a = __fdiv_rn(buf[j], S);
        row[j] = a;
        lmx = fmaxf(lmx, a); lmn = fminf(lmn, a);
    }
    red[t] = lmx; __syncthreads();
    for (int o = 128; o > 0; o >>= 1){ if (t < o) red[t] = fmaxf(red[t], red[t+o]); __syncthreads(); }
    float gm = red[0]; __syncthreads();
    red[t] = lmn; __syncthreads();
    for (int o = 128; o > 0; o >>= 1){ if (t < o) red[t] = fminf(red[t], red[t+o]); __syncthreads(); }
    if (t == 0){
        atomicMax(&g_stat[10], fenc(gm));
        atomicMin(&g_stat[11], fenc(red[0]));
    }
}

// quantize a -> bf16 aqb, fused row sums
__global__ void k_quant_a(){
    int i = blockIdx.x, bh = blockIdx.y;
    const float* row = g_dots + ((long long)bh*SEQ + i)*SEQ;
    bf16* drow = g_aqb + ((long long)bh*SEQ + i)*SEQ;
    float s, z; get_sz(5, s, z);
    float acc = 0.f;
    for (int j = threadIdx.x; j < SEQ; j += 256){
        float v = quant(row[j], s, z);
        drow[j] = __float2bfloat16(v);
        acc += v;
    }
    __shared__ float sh[256];
    sh[threadIdx.x] = acc; __syncthreads();
    for (int o = 128; o > 0; o >>= 1){ if (threadIdx.x < o) sh[threadIdx.x] += sh[threadIdx.x+o]; __syncthreads(); }
    if (threadIdx.x == 0) g_aqrowsum[bh*SEQ + i] = sh[0];
}

// ---------------- tensor-core GEMM with affine-correction epilogue ----------------
// C[i][j] = (acc - colsumB[j]*zA - rowsumA[i]*zB + zA*zB*Kconst) * ((preScale*sA)*sB) [+ bias[j]]
// TRANSB=0: B stored [k][n] (n contiguous)  -> ldmatrix.trans
// TRANSB=1: B stored [n][k] (k contiguous)  -> ldmatrix
// CMODE=1: z is (b*NH+h); C base = C + b*SEQ*ldc + h*64
template<int BM,int BN,int WM,int WN,int TRANSB,int CMODE>
__global__ void __launch_bounds__(256) k_mma(
    const bf16* __restrict__ A, int lda, long long sAz,
    const bf16* __restrict__ Bm, int ldb, long long sBz,
    float* __restrict__ C, int ldc, long long sCz,
    int K,
    const float* __restrict__ colsumB, int csz,
    const float* __restrict__ rowsumA, int rsz,
    int slotA, int slotB, float Kconst, float preScale,
    const float* __restrict__ bias)
{
    const int BK = 32;
    const int MT = BM/WM/16;
    const int NT = BN/WN/8;
    const int APAD = BK + 8;
    const int BROWS = TRANSB ? BN : BK;
    const int BPAD  = TRANSB ? (BK+8) : (BN+8);

    __shared__ __align__(16) bf16 As[BM*APAD];
    __shared__ __align__(16) bf16 Bs[BROWS*BPAD];

    int z = blockIdx.z;
    const bf16* Ab = A  + (long long)z * sAz;
    const bf16* Bb = Bm + (long long)z * sBz;
    float* Cb;
    if (CMODE == 1){
        int b = z / NH;
        int h = z - b*NH;
        Cb = C + (long long)b*SEQ*ldc + h*64;
    } else {
        Cb = C + (long long)z * sCz;
    }

    int i0 = blockIdx.y * BM, j0 = blockIdx.x * BN;
    int tid = threadIdx.x, warp = tid >> 5, lane = tid & 31;
    int wm = warp / WN, wn = warp % WN;
    int l16 = lane & 15;

    float acc[MT][NT][4];
    #pragma unroll
    for (int a = 0; a < MT; a++){
        #pragma unroll
        for (int b = 0; b < NT; b++){
            #pragma unroll
            for (int r = 0; r < 4; r++) acc[a][b][r] = 0.f;
        }
    }

    for (int k0 = 0; k0 < K; k0 += BK){
        const int AVECS = BM*BK/8;
        #pragma unroll
        for (int v = 0; v < AVECS/256; v++){
            int idx = v*256 + tid;
            int r = idx / (BK/8), c8 = idx % (BK/8);
            uint4 val = *(const uint4*)&Ab[(long long)(i0 + r)*lda + k0 + c8*8];
            *(uint4*)&As[r*APAD + c8*8] = val;
        }
        if (TRANSB){
            const int BVECS = BN*BK/8;
            #pragma unroll
            for (int v = 0; v < BVECS/256; v++){
                int idx = v*256 + tid;
                int r = idx / (BK/8), c8 = idx % (BK/8);
                uint4 val = *(const uint4*)&Bb[(long long)(j0 + r)*ldb + k0 + c8*8];
                *(uint4*)&Bs[r*BPAD + c8*8] = val;
            }
        } else {
            const int BVECS = BK*BN/8;
            #pragma unroll
            for (int v = 0; v < BVECS/256; v++){
                int idx = v*256 + tid;
                int r = idx / (BN/8), c8 = idx % (BN/8);
                uint4 val = *(const uint4*)&Bb[(long long)(k0 + r)*ldb + j0 + c8*8];
                *(uint4*)&Bs[r*BPAD + c8*8] = val;
            }
        }
        __syncthreads();

        #pragma unroll
        for (int kk = 0; kk < BK; kk += 16){
            u32 afrag[MT][4];
            #pragma unroll
            for (int mt = 0; mt < MT; mt++){
                const bf16* p = &As[(wm*MT*16 + mt*16 + l16)*APAD + kk + (lane>>4)*8];
                ldsm4(afrag[mt], p);
            }
            u32 bfrag[NT][2];
            #pragma unroll
            for (int nt = 0; nt < NT; nt++){
                if (TRANSB){
                    const bf16* p = &Bs[(wn*NT*8 + nt*8 + (l16 & 7))*BPAD + kk + ((l16>>3)&1)*8];
                    ldsm2(bfrag[nt], p);
                } else {
                    const bf16* p = &Bs[(kk + l16)*BPAD + wn*NT*8 + nt*8];
                    ldsm2t(bfrag[nt], p);
                }
            }
            #pragma unroll
            for (int mt = 0; mt < MT; mt++){
                #pragma unroll
                for (int nt = 0; nt < NT; nt++)
                    mma16816(acc[mt][nt], afrag[mt], bfrag[nt]);
            }
        }
        __syncthreads();
    }

    float sA, zA, sB, zB;
    get_sz(slotA, sA, zA); get_sz(slotB, sB, zB);
    float mult  = (preScale * sA) * sB;
    float cterm = (zA * zB) * Kconst;
    const float* cs = colsumB + (long long)z*csz;
    const float* rs = rowsumA + (long long)z*rsz;

    #pragma unroll
    for (int mt = 0; mt < MT; mt++){
        int row0 = i0 + wm*MT*16 + mt*16 + (lane>>2);
        float rs0 = rs[row0], rs1 = rs[row0+8];
        #pragma unroll
        for (int nt = 0; nt < NT; nt++){
            int col0 = j0 + wn*NT*8 + nt*8 + (lane&3)*2;
            float cs0 = cs[col0], cs1 = cs[col0+1];
            float b0 = bias ? bias[col0]   : 0.f;
            float b1 = bias ? bias[col0+1] : 0.f;
            float v0 = (acc[mt][nt][0] - cs0*zA - rs0*zB + cterm)*mult + b0;
            float v1 = (acc[mt][nt][1] - cs1*zA - rs0*zB + cterm)*mult + b1;
            float v2 = (acc[mt][nt][2] - cs0*zA - rs1*zB + cterm)*mult + b0;
            float v3 = (acc[mt][nt][3] - cs1*zA - rs1*zB + cterm)*mult + b1;
            Cb[(long long)row0*ldc + col0]       = v0;
            Cb[(long long)row0*ldc + col0 + 1]   = v1;
            Cb[(long long)(row0+8)*ldc + col0]   = v2;
            Cb[(long long)(row0+8)*ldc + col0+1] = v3;
        }
    }
}

// ---------------- launcher ----------------
extern "C" void kernel_launch(void* const* d_in, const int* in_sizes, int n_in,
                              void* d_out, int out_size){
    const float *x = 0, *wqkv = 0, *wout = 0, *bout = 0;
    for (int i = 0; i < n_in; i++){
        if      (in_sizes[i] == MROWS*DMODEL)  x    = (const float*)d_in[i];
        else if (in_sizes[i] == J3*DMODEL)     wqkv = (const float*)d_in[i];
        else if (in_sizes[i] == DMODEL*DMODEL) wout = (const float*)d_in[i];
        else if (in_sizes[i] == DMODEL)        bout = (const float*)d_in[i];
    }
    float* out = (float*)d_out;

    bf16 *p_xq, *p_wq1, *p_wq2, *p_qb, *p_kb, *p_vb, *p_aqb;
    float *p_xqkv, *p_dots, *p_outbuf;
    float *p_rowsum_x, *p_colsum_w1, *p_colsum_w2, *p_xqkvsum;
    float *p_rowsumq, *p_colsumk, *p_vcolsum, *p_aqrowsum;
    cudaGetSymbolAddress((void**)&p_xq,        g_xq);
    cudaGetSymbolAddress((void**)&p_wq1,       g_wq1);
    cudaGetSymbolAddress((void**)&p_wq2,       g_wq2);
    cudaGetSymbolAddress((void**)&p_qb,        g_qb);
    cudaGetSymbolAddress((void**)&p_kb,        g_kb);
    cudaGetSymbolAddress((void**)&p_vb,        g_vb);
    cudaGetSymbolAddress((void**)&p_aqb,       g_aqb);
    cudaGetSymbolAddress((void**)&p_xqkv,      g_xqkv);
    cudaGetSymbolAddress((void**)&p_dots,      g_dots);
    cudaGetSymbolAddress((void**)&p_outbuf,    g_outbuf);
    cudaGetSymbolAddress((void**)&p_rowsum_x,  g_rowsum_x);
    cudaGetSymbolAddress((void**)&p_colsum_w1, g_colsum_w1);
    cudaGetSymbolAddress((void**)&p_colsum_w2, g_colsum_w2);
    cudaGetSymbolAddress((void**)&p_xqkvsum,   g_xqkvsum);
    cudaGetSymbolAddress((void**)&p_rowsumq,   g_rowsumq);
    cudaGetSymbolAddress((void**)&p_colsumk,   g_colsumk);
    cudaGetSymbolAddress((void**)&p_vcolsum,   g_vcolsum);
    cudaGetSymbolAddress((void**)&p_aqrowsum,  g_aqrowsum);

    k_init<<<1, 256>>>();
    k_minmax<<<1024, 256>>>(x,    MROWS*DMODEL, 0);
    k_minmax<<<1024, 256>>>(wqkv, J3*DMODEL,    1);
    k_quantrow<<<MROWS, 256>>>(x, p_xq, p_rowsum_x, 0, DMODEL);
    k_quantW<<<J3, 256>>>(wqkv, p_wq1, p_colsum_w1, 1, DMODEL, J3);
    // QKV projection: [4096x768] @ [768x2304]
    k_mma<128,128,2,4,0,0><<<dim3(J3/128, MROWS/128, 1), 256>>>(
        p_xq, DMODEL, 0, p_wq1, J3, 0, p_xqkv, J3, 0, DMODEL,
        p_colsum_w1, 0, p_rowsum_x, 0, 0, 1, (float)DMODEL, 1.0f, (const float*)0);
    k_rowsum<<<MROWS, 256>>>(p_xqkv, p_xqkvsum, J3);
    k_minmax3<<<1024, 256>>>();
    k_pack_qkv<<<dim3(SEQ/4, BHN), 256>>>();
    // dots: per (b,h)  [1024x64] @ [64x1024] (B stored [n][k])
    k_mma<128,128,2,4,1,0><<<dim3(SEQ/128, SEQ/128, BHN), 256>>>(
        p_qb, DHD, (long long)SEQ*DHD, p_kb, DHD, (long long)SEQ*DHD,
        p_dots, SEQ, (long long)SEQ*SEQ, DHD,
        p_colsumk, SEQ, p_rowsumq, SEQ, 2, 3, 0.0f, 0.125f, (const float*)0);
    k_softmax<<<dim3(SEQ, BHN), 256>>>();
    k_quant_a<<<dim3(SEQ, BHN), 256>>>();
    // AV: per (b,h)  [1024x1024] @ [1024x64] (B stored [k][n])
    k_mma<128,64,4,2,0,1><<<dim3(1, SEQ/128, BHN), 256>>>(
        p_aqb, SEQ, (long long)SEQ*SEQ, p_vb, DHD, (long long)SEQ*DHD,
        p_outbuf, DMODEL, 0, SEQ,
        p_vcolsum, DHD, p_aqrowsum, SEQ, 5, 4, (float)SEQ, 1.0f, (const float*)0);
    k_minmax<<<1024, 256>>>(p_outbuf, MROWS*DMODEL,  6);
    k_minmax<<<1024, 256>>>(wout,     DMODEL*DMODEL, 7);
    k_quantrow<<<MROWS, 256>>>(p_outbuf, p_xq, p_rowsum_x /*dummy*/, 6, DMODEL);
    k_quantW<<<DMODEL, 256>>>(wout, p_wq2, p_colsum_w2, 7, DMODEL, DMODEL);
    // output projection: [4096x768] @ [768x768] + bias (rowsum uses xqkvsum — faithful to ref)
    k_mma<128,128,2,4,0,0><<<dim3(DMODEL/128, MROWS/128, 1), 256>>>(
        p_xq, DMODEL, 0, p_wq2, DMODEL, 0, out, DMODEL, 0, DMODEL,
        p_colsum_w2, 0, p_xqkvsum, 0, 6, 7, (float)J3, 1.0f, bout);
}

// round 5
// speedup vs baseline: 5.7605x; 1.6134x over previous
#include <cuda_runtime.h>
#include <cuda_bf16.h>
#include <cstdint>
#include <cstddef>
#include <math.h>

#define NB      4
#define SEQ     1024
#define DMODEL  768
#define NH      12
#define DHD     64
#define J3      2304
#define MROWS   4096          // NB*SEQ
#define BHN     48            // NB*NH

typedef __nv_bfloat16 bf16;
typedef unsigned int  u32;

// ---------------- scratch ----------------
__device__ __align__(16) bf16  g_xq[MROWS*DMODEL];          // quantized x / quantized attn-out (bf16)
__device__ __align__(16) bf16  g_wq1[DMODEL*J3];            // quantized w_qkv^T  [k][n]
__device__ __align__(16) bf16  g_wq2[DMODEL*DMODEL];        // quantized w_out^T  [k][n]
__device__ __align__(16) float g_xqkv[MROWS*J3];            // qkv projection output (f32)
__device__ __align__(16) bf16  g_qb[BHN*SEQ*DHD];           // packed quantized q
__device__ __align__(16) bf16  g_kb[BHN*SEQ*DHD];           // packed quantized k
__device__ __align__(16) bf16  g_vb[BHN*SEQ*DHD];           // packed quantized v
__device__ __align__(16) float g_outbuf[MROWS*DMODEL];      // attention output (b,n,h*64+d)
__device__ float    g_rowsum_x[MROWS];
__device__ float    g_colsum_w1[J3];
__device__ float    g_colsum_w2[DMODEL];
__device__ float    g_xqkvsum[MROWS];                       // atomically accumulated in gemm1 epilogue
__device__ float    g_rowsumq[BHN*SEQ];
__device__ float    g_colsumk[BHN*SEQ];
__device__ float    g_vcolsum[BHN*DHD];
__device__ float    g_rowm[BHN*SEQ];                        // softmax row max
__device__ float    g_rowS[BHN*SEQ];                        // softmax row sum-exp
__device__ unsigned g_stat[16];   // slot*2=max(enc), slot*2+1=min(enc). slots:0=x 1=w1 2=q 3=k 4=v 5=a 6=out 7=w2

// ---------------- helpers ----------------
__device__ __forceinline__ unsigned fenc(float f){
    unsigned u = __float_as_uint(f);
    return (u & 0x80000000u) ? ~u : (u | 0x80000000u);
}
__device__ __forceinline__ float fdec(unsigned e){
    return (e & 0x80000000u) ? __uint_as_float(e ^ 0x80000000u) : __uint_as_float(~e);
}
__device__ __forceinline__ void get_sz(int slot, float& s, float& z){
    float mx = fdec(g_stat[2*slot]);
    float mn = fdec(g_stat[2*slot+1]);
    s = __fdiv_rn(mx - mn, 15.0f);
    z = rintf(15.0f - __fdiv_rn(mx, s));
}
__device__ __forceinline__ float quant(float v, float s, float z){
    return rintf(__fdiv_rn(v, s) + z);
}
__device__ __forceinline__ u32 packbf2(float lo, float hi){
    __nv_bfloat162 t = __floats2bfloat162_rn(lo, hi);
    return *reinterpret_cast<u32*>(&t);
}

__device__ __forceinline__ void ldsm4(u32* r, const void* p){
    u32 a = (u32)__cvta_generic_to_shared(p);
    asm volatile("ldmatrix.sync.aligned.m8n8.x4.shared.b16 {%0,%1,%2,%3},[%4];"
        : "=r"(r[0]),"=r"(r[1]),"=r"(r[2]),"=r"(r[3]) : "r"(a));
}
__device__ __forceinline__ void ldsm2(u32* r, const void* p){
    u32 a = (u32)__cvta_generic_to_shared(p);
    asm volatile("ldmatrix.sync.aligned.m8n8.x2.shared.b16 {%0,%1},[%2];"
        : "=r"(r[0]),"=r"(r[1]) : "r"(a));
}
__device__ __forceinline__ void ldsm2t(u32* r, const void* p){
    u32 a = (u32)__cvta_generic_to_shared(p);
    asm volatile("ldmatrix.sync.aligned.m8n8.x2.trans.shared.b16 {%0,%1},[%2];"
        : "=r"(r[0]),"=r"(r[1]) : "r"(a));
}
__device__ __forceinline__ void mma16816(float* c, const u32* a, const u32* b){
    asm volatile("mma.sync.aligned.m16n8k16.row.col.f32.bf16.bf16.f32 "
        "{%0,%1,%2,%3}, {%4,%5,%6,%7}, {%8,%9}, {%0,%1,%2,%3};"
        : "+f"(c[0]),"+f"(c[1]),"+f"(c[2]),"+f"(c[3])
        : "r"(a[0]),"r"(a[1]),"r"(a[2]),"r"(a[3]), "r"(b[0]),"r"(b[1]));
}
__device__ __forceinline__ float qsum(float v){       // reduce over the 4 lanes of a quad
    v += __shfl_xor_sync(0xffffffffu, v, 1);
    v += __shfl_xor_sync(0xffffffffu, v, 2);
    return v;
}
__device__ __forceinline__ float qmax(float v){
    v = fmaxf(v, __shfl_xor_sync(0xffffffffu, v, 1));
    v = fmaxf(v, __shfl_xor_sync(0xffffffffu, v, 2));
    return v;
}
__device__ __forceinline__ float qmin(float v){
    v = fminf(v, __shfl_xor_sync(0xffffffffu, v, 1));
    v = fminf(v, __shfl_xor_sync(0xffffffffu, v, 2));
    return v;
}

// ---------------- elementwise kernels ----------------
__global__ void k_init(){
    int t = threadIdx.x;
    if (t < 8){ g_stat[2*t] = fenc(-INFINITY); g_stat[2*t+1] = fenc(INFINITY); }
    for (int i = t; i < BHN*DHD; i += blockDim.x) g_vcolsum[i] = 0.f;
    for (int i = t; i < MROWS;   i += blockDim.x) g_xqkvsum[i] = 0.f;
}

__global__ void k_minmax(const float* __restrict__ p, int n, int slot){
    float mx = -INFINITY, mn = INFINITY;
    for (int i = blockIdx.x*blockDim.x + threadIdx.x; i < n; i += gridDim.x*blockDim.x){
        float v = p[i]; mx = fmaxf(mx, v); mn = fminf(mn, v);
    }
    __shared__ float smx[256], smn[256];
    int t = threadIdx.x;
    smx[t] = mx; smn[t] = mn; __syncthreads();
    for (int o = 128; o > 0; o >>= 1){
        if (t < o){ smx[t] = fmaxf(smx[t], smx[t+o]); smn[t] = fminf(smn[t], smn[t+o]); }
        __syncthreads();
    }
    if (t == 0){
        atomicMax(&g_stat[2*slot],   fenc(smx[0]));
        atomicMin(&g_stat[2*slot+1], fenc(smn[0]));
    }
}

// quantize rows -> bf16, fused row sums
__global__ void k_quantrow(const float* __restrict__ src, bf16* __restrict__ dst,
                           float* __restrict__ rowsum, int slot, int rowlen){
    int r = blockIdx.x;
    float s, z; get_sz(slot, s, z);
    float acc = 0.f;
    for (int c = threadIdx.x; c < rowlen; c += blockDim.x){
        float v = quant(src[(long long)r*rowlen + c], s, z);
        dst[(long long)r*rowlen + c] = __float2bfloat16(v);
        acc += v;
    }
    __shared__ float sh[256];
    sh[threadIdx.x] = acc; __syncthreads();
    for (int o = 128; o > 0; o >>= 1){ if (threadIdx.x < o) sh[threadIdx.x] += sh[threadIdx.x+o]; __syncthreads(); }
    if (threadIdx.x == 0) rowsum[r] = sh[0];
}

// quantize weight [Ncols][K] into transposed bf16 wq [K][Ncols], fused col sums
__global__ void k_quantW(const float* __restrict__ w, bf16* __restrict__ wq,
                         float* __restrict__ colsum, int slot, int K, int Ncols){
    int j = blockIdx.x;
    float s, z; get_sz(slot, s, z);
    float acc = 0.f;
    for (int d = threadIdx.x; d < K; d += blockDim.x){
        float v = quant(w[(long long)j*K + d], s, z);
        wq[(long long)d*Ncols + j] = __float2bfloat16(v);
        acc += v;
    }
    __shared__ float sh[256];
    sh[threadIdx.x] = acc; __syncthreads();
    for (int o = 128; o > 0; o >>= 1){ if (threadIdx.x < o) sh[threadIdx.x] += sh[threadIdx.x+o]; __syncthreads(); }
    if (threadIdx.x == 0) colsum[j] = sh[0];
}

// pack quantized q/k/v into head-contiguous bf16 buffers; fused token-sums + v colsum atomics
__global__ void k_pack_qkv(){
    int bh = blockIdx.y;
    int b = bh / NH, h = bh - b*NH;
    int t = threadIdx.x;           // 256 = 4 tokens x 64 d
    int dtok = t >> 6, d = t & 63;
    int n = blockIdx.x*4 + dtok;
    float sq, zq, sk, zk, sv, zv;
    get_sz(2, sq, zq); get_sz(3, sk, zk); get_sz(4, sv, zv);
    long long base = (long long)(b*SEQ + n)*J3 + h*DHD + d;
    float qv = quant(g_xqkv[base],            sq, zq);
    float kv = quant(g_xqkv[base + DMODEL],   sk, zk);
    float vv = quant(g_xqkv[base + 2*DMODEL], sv, zv);
    long long po = ((long long)bh*SEQ + n)*DHD + d;
    g_qb[po] = __float2bfloat16(qv);
    g_kb[po] = __float2bfloat16(kv);
    g_vb[po] = __float2bfloat16(vv);
    __shared__ float shq[256], shk[256], shv[256];
    shq[t] = qv; shk[t] = kv; shv[t] = vv; __syncthreads();
    for (int o = 32; o > 0; o >>= 1){
        if (d < o){ shq[t] += shq[t+o]; shk[t] += shk[t+o]; }
        __syncthreads();
    }
    if (d == 0){
        g_rowsumq[bh*SEQ + n] = shq[t];
        g_colsumk[bh*SEQ + n] = shk[t];
    }
    if (t < 64){
        float s = shv[t] + shv[t+64] + shv[t+128] + shv[t+192];
        atomicAdd(&g_vcolsum[bh*DHD + t], s);
    }
}

// ---------------- fused attention: stats pass ----------------
// Per block: one (b,h), 128 q rows. Streams 8 K tiles; computes dots in register
// fragments, online rowmax/rowmin/rowsumexp. Writes m,S; atomics for global a min/max.
__global__ void __launch_bounds__(256) k_attn_stats(){
    __shared__ __align__(16) bf16 Qs[128*72];
    __shared__ __align__(16) bf16 Ks[128*72];
    __shared__ float csk_s[128];
    __shared__ float redx[256], redn[256];

    int bh = blockIdx.y, qt = blockIdx.x;
    int tid = threadIdx.x, warp = tid >> 5, lane = tid & 31;
    int l16 = lane & 15;

    float sq, zq, sk, zk;
    get_sz(2, sq, zq); get_sz(3, sk, zk);
    float s3 = (0.125f * sq) * sk;

    // load Q tile
    for (int it = 0; it < 4; it++){
        int idx = it*256 + tid;
        int r = idx >> 3, c8 = idx & 7;
        uint4 v = *(const uint4*)&g_qb[((long long)bh*SEQ + qt*128 + r)*DHD + c8*8];
        *(uint4*)&Qs[r*72 + c8*8] = v;
    }

    int r0 = warp*16 + (lane>>2), r1 = r0 + 8;
    float rsq0 = g_rowsumq[bh*SEQ + qt*128 + r0];
    float rsq1 = g_rowsumq[bh*SEQ + qt*128 + r1];

    float m0 = -INFINITY, m1 = -INFINITY;
    float n0 =  INFINITY, n1 =  INFINITY;
    float S0 = 0.f, S1 = 0.f;

    for (int kt = 0; kt < 8; kt++){
        __syncthreads();
        for (int it = 0; it < 4; it++){
            int idx = it*256 + tid;
            int r = idx >> 3, c8 = idx & 7;
            uint4 v = *(const uint4*)&g_kb[((long long)bh*SEQ + kt*128 + r)*DHD + c8*8];
            *(uint4*)&Ks[r*72 + c8*8] = v;
        }
        if (tid < 128) csk_s[tid] = g_colsumk[bh*SEQ + kt*128 + tid];
        __syncthreads();

        float acc[16][4];
        #pragma unroll
        for (int nt = 0; nt < 16; nt++){ acc[nt][0]=0.f; acc[nt][1]=0.f; acc[nt][2]=0.f; acc[nt][3]=0.f; }

        #pragma unroll
        for (int kk = 0; kk < 64; kk += 16){
            u32 af[4];
            ldsm4(af, &Qs[(warp*16 + l16)*72 + kk + (lane>>4)*8]);
            #pragma unroll
            for (int nt = 0; nt < 16; nt++){
                u32 bf[2];
                ldsm2(bf, &Ks[(nt*8 + (l16&7))*72 + kk + ((l16>>3)&1)*8]);
                mma16816(acc[nt], af, bf);
            }
        }

        // corrections -> d in-place
        int c = (lane&3)*2;
        #pragma unroll
        for (int nt = 0; nt < 16; nt++){
            int cg = nt*8 + c;
            float cz0 = csk_s[cg]*zq, cz1 = csk_s[cg+1]*zq;
            acc[nt][0] = (acc[nt][0] - cz0 - rsq0*zk)*s3;
            acc[nt][1] = (acc[nt][1] - cz1 - rsq0*zk)*s3;
            acc[nt][2] = (acc[nt][2] - cz0 - rsq1*zk)*s3;
            acc[nt][3] = (acc[nt][3] - cz1 - rsq1*zk)*s3;
        }
        // row stats
        float tx0=-INFINITY, tx1=-INFINITY, tn0=INFINITY, tn1=INFINITY;
        #pragma unroll
        for (int nt = 0; nt < 16; nt++){
            tx0 = fmaxf(tx0, fmaxf(acc[nt][0], acc[nt][1]));
            tx1 = fmaxf(tx1, fmaxf(acc[nt][2], acc[nt][3]));
            tn0 = fminf(tn0, fminf(acc[nt][0], acc[nt][1]));
            tn1 = fminf(tn1, fminf(acc[nt][2], acc[nt][3]));
        }
        tx0 = qmax(tx0); tx1 = qmax(tx1);
        tn0 = qmin(tn0); tn1 = qmin(tn1);
        float nm0 = fmaxf(m0, tx0), nm1 = fmaxf(m1, tx1);
        float se0 = 0.f, se1 = 0.f;
        #pragma unroll
        for (int nt = 0; nt < 16; nt++){
            se0 += expf(acc[nt][0]-nm0) + expf(acc[nt][1]-nm0);
            se1 += expf(acc[nt][2]-nm1) + expf(acc[nt][3]-nm1);
        }
        se0 = qsum(se0); se1 = qsum(se1);
        S0 = S0*expf(m0-nm0) + se0;  m0 = nm0;  n0 = fminf(n0, tn0);
        S1 = S1*expf(m1-nm1) + se1;  m1 = nm1;  n1 = fminf(n1, tn1);
    }

    if ((lane & 3) == 0){
        g_rowm[bh*SEQ + qt*128 + r0] = m0;  g_rowS[bh*SEQ + qt*128 + r0] = S0;
        g_rowm[bh*SEQ + qt*128 + r1] = m1;  g_rowS[bh*SEQ + qt*128 + r1] = S1;
    }
    // global a min/max candidates: amax_row = 1/S, amin_row = exp(mn-m)/S
    float ax = fmaxf(__fdiv_rn(1.0f, S0), __fdiv_rn(1.0f, S1));
    float an = fminf(__fdiv_rn(expf(n0 - m0), S0), __fdiv_rn(expf(n1 - m1), S1));
    redx[tid] = ax; redn[tid] = an; __syncthreads();
    for (int o = 128; o > 0; o >>= 1){
        if (tid < o){ redx[tid] = fmaxf(redx[tid], redx[tid+o]); redn[tid] = fminf(redn[tid], redn[tid+o]); }
        __syncthreads();
    }
    if (tid == 0){
        atomicMax(&g_stat[10], fenc(redx[0]));
        atomicMin(&g_stat[11], fenc(redn[0]));
    }
}

// ---------------- fused attention: recompute + quantize + AV ----------------
__global__ void __launch_bounds__(256) k_attn_av(){
    __shared__ __align__(16) bf16 Qs[128*72];
    __shared__ __align__(16) bf16 KVs[128*72];   // K tile, then V tile
    __shared__ float csk_s[128];
    __shared__ float vcs_s[64];

    int bh = blockIdx.y, qt = blockIdx.x;
    int b = bh / NH, h = bh - b*NH;
    int tid = threadIdx.x, warp = tid >> 5, lane = tid & 31;
    int l16 = lane & 15;

    float sq, zq, sk, zk, sv, zv, sa, za;
    get_sz(2, sq, zq); get_sz(3, sk, zk); get_sz(4, sv, zv); get_sz(5, sa, za);
    float s3 = (0.125f * sq) * sk;

    for (int it = 0; it < 4; it++){
        int idx = it*256 + tid;
        int r = idx >> 3, c8 = idx & 7;
        uint4 v = *(const uint4*)&g_qb[((long long)bh*SEQ + qt*128 + r)*DHD + c8*8];
        *(uint4*)&Qs[r*72 + c8*8] = v;
    }
    if (tid < 64) vcs_s[tid] = g_vcolsum[bh*DHD + tid];

    int r0 = warp*16 + (lane>>2), r1 = r0 + 8;
    float rsq0 = g_rowsumq[bh*SEQ + qt*128 + r0];
    float rsq1 = g_rowsumq[bh*SEQ + qt*128 + r1];
    float m0 = g_rowm[bh*SEQ + qt*128 + r0], S0 = g_rowS[bh*SEQ + qt*128 + r0];
    float m1 = g_rowm[bh*SEQ + qt*128 + r1], S1 = g_rowS[bh*SEQ + qt*128 + r1];

    float oacc[8][4];
    #pragma unroll
    for (int nt = 0; nt < 8; nt++){ oacc[nt][0]=0.f; oacc[nt][1]=0.f; oacc[nt][2]=0.f; oacc[nt][3]=0.f; }
    float aqs0 = 0.f, aqs1 = 0.f;

    for (int kt = 0; kt < 8; kt++){
        __syncthreads();
        for (int it = 0; it < 4; it++){
            int idx = it*256 + tid;
            int r = idx >> 3, c8 = idx & 7;
            uint4 v = *(const uint4*)&g_kb[((long long)bh*SEQ + kt*128 + r)*DHD + c8*8];
            *(uint4*)&KVs[r*72 + c8*8] = v;
        }
        if (tid < 128) csk_s[tid] = g_colsumk[bh*SEQ + kt*128 + tid];
        __syncthreads();

        float acc[16][4];
        #pragma unroll
        for (int nt = 0; nt < 16; nt++){ acc[nt][0]=0.f; acc[nt][1]=0.f; acc[nt][2]=0.f; acc[nt][3]=0.f; }
        #pragma unroll
        for (int kk = 0; kk < 64; kk += 16){
            u32 af[4];
            ldsm4(af, &Qs[(warp*16 + l16)*72 + kk + (lane>>4)*8]);
            #pragma unroll
            for (int nt = 0; nt < 16; nt++){
                u32 bf[2];
                ldsm2(bf, &KVs[(nt*8 + (l16&7))*72 + kk + ((l16>>3)&1)*8]);
                mma16816(acc[nt], af, bf);
            }
        }

        int c = (lane&3)*2;
        #pragma unroll
        for (int nt = 0; nt < 16; nt++){
            int cg = nt*8 + c;
            float cz0 = csk_s[cg]*zq, cz1 = csk_s[cg+1]*zq;
            acc[nt][0] = (acc[nt][0] - cz0 - rsq0*zk)*s3;
            acc[nt][1] = (acc[nt][1] - cz1 - rsq0*zk)*s3;
            acc[nt][2] = (acc[nt][2] - cz0 - rsq1*zk)*s3;
            acc[nt][3] = (acc[nt][3] - cz1 - rsq1*zk)*s3;
        }

        __syncthreads();   // dots mma done reading K tile
        for (int it = 0; it < 4; it++){
            int idx = it*256 + tid;
            int r = idx >> 3, c8 = idx & 7;
            uint4 v = *(const uint4*)&g_vb[((long long)bh*SEQ + kt*128 + r)*DHD + c8*8];
            *(uint4*)&KVs[r*72 + c8*8] = v;
        }
        __syncthreads();

        // quantize a in-register, form P frags (C->A layout identity), mma with V
        #pragma unroll
        for (int j = 0; j < 8; j++){
            float q00, q01, q02, q03, q10, q11, q12, q13;
            {
                float a0 = __fdiv_rn(expf(acc[2*j][0]   - m0), S0);
                float a1 = __fdiv_rn(expf(acc[2*j][1]   - m0), S0);
                float a2 = __fdiv_rn(expf(acc[2*j][2]   - m1), S1);
                float a3 = __fdiv_rn(expf(acc[2*j][3]   - m1), S1);
                q00 = quant(a0, sa, za); q01 = quant(a1, sa, za);
                q02 = quant(a2, sa, za); q03 = quant(a3, sa, za);
                float b0 = __fdiv_rn(expf(acc[2*j+1][0] - m0), S0);
                float b1 = __fdiv_rn(expf(acc[2*j+1][1] - m0), S0);
                float b2 = __fdiv_rn(expf(acc[2*j+1][2] - m1), S1);
                float b3 = __fdiv_rn(expf(acc[2*j+1][3] - m1), S1);
                q10 = quant(b0, sa, za); q11 = quant(b1, sa, za);
                q12 = quant(b2, sa, za); q13 = quant(b3, sa, za);
            }
            aqs0 += q00 + q01 + q10 + q11;
            aqs1 += q02 + q03 + q12 + q13;
            u32 pa[4];
            pa[0] = packbf2(q00, q01);
            pa[1] = packbf2(q02, q03);
            pa[2] = packbf2(q10, q11);
            pa[3] = packbf2(q12, q13);
            #pragma unroll
            for (int nt = 0; nt < 8; nt++){
                u32 vf[2];
                ldsm2t(vf, &KVs[(16*j + l16)*72 + nt*8]);
                mma16816(oacc[nt], pa, vf);
            }
        }
    }

    // full-row aq sums (exact integer sums; quad lanes hold disjoint columns)
    aqs0 = qsum(aqs0);
    aqs1 = qsum(aqs1);

    float mult  = sa * sv;
    float cterm = (za * zv) * (float)SEQ;
    int c = (lane&3)*2;
    long long ob0 = (long long)(b*SEQ + qt*128 + r0)*DMODEL + h*DHD;
    long long ob1 = (long long)(b*SEQ + qt*128 + r1)*DMODEL + h*DHD;
    #pragma unroll
    for (int nt = 0; nt < 8; nt++){
        int d0 = nt*8 + c;
        float w0 = vcs_s[d0]*za, w1 = vcs_s[d0+1]*za;
        g_outbuf[ob0 + d0]     = (oacc[nt][0] - w0 - aqs0*zv + cterm)*mult;
        g_outbuf[ob0 + d0 + 1] = (oacc[nt][1] - w1 - aqs0*zv + cterm)*mult;
        g_outbuf[ob1 + d0]     = (oacc[nt][2] - w0 - aqs1*zv + cterm)*mult;
        g_outbuf[ob1 + d0 + 1] = (oacc[nt][3] - w1 - aqs1*zv + cterm)*mult;
    }
}

// ---------------- tensor-core GEMM with affine-correction epilogue ----------------
// C[i][j] = (acc - colsumB[j]*zA - rowsumA[i]*zB + zA*zB*Kconst) * (sA*sB) [+ bias[j]]
// B stored [k][n] (n contiguous). F1: fuse xqkv rowsum atomics + q/k/v region minmax.
template<int F1>
__global__ void __launch_bounds__(256) k_mma(
    const bf16* __restrict__ A, int lda,
    const bf16* __restrict__ Bm, int ldb,
    float* __restrict__ C, int ldc,
    int K,
    const float* __restrict__ colsumB,
    const float* __restrict__ rowsumA,
    int slotA, int slotB, float Kconst,
    const float* __restrict__ bias)
{
    const int BM = 128, BN = 128, BK = 32;
    const int MT = 4, NT = 4;       // 8 warps as 2x4; warp tile 64x32
    const int APAD = BK + 8;
    const int BPAD = BN + 8;

    __shared__ __align__(16) bf16 As[BM*APAD];
    __shared__ __align__(16) bf16 Bs[BK*BPAD];
    __shared__ float redx[256], redn[256];

    int i0 = blockIdx.y * BM, j0 = blockIdx.x * BN;
    int tid = threadIdx.x, warp = tid >> 5, lane = tid & 31;
    int wm = warp >> 2, wn = warp & 3;
    int l16 = lane & 15;

    float acc[MT][NT][4];
    #pragma unroll
    for (int a = 0; a < MT; a++)
        #pragma unroll
        for (int b = 0; b < NT; b++){
            acc[a][b][0]=0.f; acc[a][b][1]=0.f; acc[a][b][2]=0.f; acc[a][b][3]=0.f;
        }

    for (int k0 = 0; k0 < K; k0 += BK){
        #pragma unroll
        for (int v = 0; v < 2; v++){
            int idx = v*256 + tid;
            int r = idx >> 2, c8 = idx & 3;
            uint4 val = *(const uint4*)&A[(long long)(i0 + r)*lda + k0 + c8*8];
            *(uint4*)&As[r*APAD + c8*8] = val;
        }
        #pragma unroll
        for (int v = 0; v < 2; v++){
            int idx = v*256 + tid;
            int r = idx >> 4, c8 = idx & 15;
            uint4 val = *(const uint4*)&Bm[(long long)(k0 + r)*ldb + j0 + c8*8];
            *(uint4*)&Bs[r*BPAD + c8*8] = val;
        }
        __syncthreads();

        #pragma unroll
        for (int kk = 0; kk < BK; kk += 16){
            u32 af[MT][4];
            #pragma unroll
            for (int mt = 0; mt < MT; mt++)
                ldsm4(af[mt], &As[(wm*64 + mt*16 + l16)*APAD + kk + (lane>>4)*8]);
            u32 bf[NT][2];
            #pragma unroll
            for (int nt = 0; nt < NT; nt++)
                ldsm2t(bf[nt], &Bs[(kk + l16)*BPAD + wn*32 + nt*8]);
            #pragma unroll
            for (int mt = 0; mt < MT; mt++)
                #pragma unroll
                for (int nt = 0; nt < NT; nt++)
                    mma16816(acc[mt][nt], af[mt], bf[nt]);
        }
        __syncthreads();
    }

    float sA, zA, sB, zB;
    get_sz(slotA, sA, zA); get_sz(slotB, sB, zB);
    float mult  = sA * sB;
    float cterm = (zA * zB) * Kconst;

    float lmx = -INFINITY, lmn = INFINITY;

    #pragma unroll
    for (int mt = 0; mt < MT; mt++){
        int row0 = i0 + wm*64 + mt*16 + (lane>>2);
        float rs0 = rowsumA[row0], rs1 = rowsumA[row0+8];
        float p0 = 0.f, p8 = 0.f;
        #pragma unroll
        for (int nt = 0; nt < NT; nt++){
            int col0 = j0 + wn*32 + nt*8 + (lane&3)*2;
            float cs0 = colsumB[col0], cs1 = colsumB[col0+1];
            float b0 = bias ? bias[col0]   : 0.f;
            float b1 = bias ? bias[col0+1] : 0.f;
            float v0 = (acc[mt][nt][0] - cs0*zA - rs0*zB + cterm)*mult + b0;
            float v1 = (acc[mt][nt][1] - cs1*zA - rs0*zB + cterm)*mult + b1;
            float v2 = (acc[mt][nt][2] - cs0*zA - rs1*zB + cterm)*mult + b0;
            float v3 = (acc[mt][nt][3] - cs1*zA - rs1*zB + cterm)*mult + b1;
            C[(long long)row0*ldc + col0]       = v0;
            C[(long long)row0*ldc + col0 + 1]   = v1;
            C[(long long)(row0+8)*ldc + col0]   = v2;
            C[(long long)(row0+8)*ldc + col0+1] = v3;
            if (F1){
                p0 += v0 + v1; p8 += v2 + v3;
                lmx = fmaxf(lmx, fmaxf(fmaxf(v0,v1), fmaxf(v2,v3)));
                lmn = fminf(lmn, fminf(fminf(v0,v1), fminf(v2,v3)));
            }
        }
        if (F1){
            p0 = qsum(p0); p8 = qsum(p8);
            if ((lane & 3) == 0){
                atomicAdd(&g_xqkvsum[row0],   p0);
                atomicAdd(&g_xqkvsum[row0+8], p8);
            }
        }
    }

    if (F1){
        redx[tid] = lmx; redn[tid] = lmn; __syncthreads();
        for (int o = 128; o > 0; o >>= 1){
            if (tid < o){ redx[tid] = fmaxf(redx[tid], redx[tid+o]); redn[tid] = fminf(redn[tid], redn[tid+o]); }
            __syncthreads();
        }
        if (tid == 0){
            int region = blockIdx.x / 6;    // 6 blocks of 128 per 768-wide region
            atomicMax(&g_stat[2*(2+region)],   fenc(redx[0]));
            atomicMin(&g_stat[2*(2+region)+1], fenc(redn[0]));
        }
    }
}

// ---------------- launcher ----------------
extern "C" void kernel_launch(void* const* d_in, const int* in_sizes, int n_in,
                              void* d_out, int out_size){
    const float *x = 0, *wqkv = 0, *wout = 0, *bout = 0;
    for (int i = 0; i < n_in; i++){
        if      (in_sizes[i] == MROWS*DMODEL)  x    = (const float*)d_in[i];
        else if (in_sizes[i] == J3*DMODEL)     wqkv = (const float*)d_in[i];
        else if (in_sizes[i] == DMODEL*DMODEL) wout = (const float*)d_in[i];
        else if (in_sizes[i] == DMODEL)        bout = (const float*)d_in[i];
    }
    float* out = (float*)d_out;

    bf16 *p_xq, *p_wq1, *p_wq2;
    float *p_xqkv, *p_outbuf;
    float *p_rowsum_x, *p_colsum_w1, *p_colsum_w2, *p_xqkvsum;
    cudaGetSymbolAddress((void**)&p_xq,        g_xq);
    cudaGetSymbolAddress((void**)&p_wq1,       g_wq1);
    cudaGetSymbolAddress((void**)&p_wq2,       g_wq2);
    cudaGetSymbolAddress((void**)&p_xqkv,      g_xqkv);
    cudaGetSymbolAddress((void**)&p_outbuf,    g_outbuf);
    cudaGetSymbolAddress((void**)&p_rowsum_x,  g_rowsum_x);
    cudaGetSymbolAddress((void**)&p_colsum_w1, g_colsum_w1);
    cudaGetSymbolAddress((void**)&p_colsum_w2, g_colsum_w2);
    cudaGetSymbolAddress((void**)&p_xqkvsum,   g_xqkvsum);

    k_init<<<1, 256>>>();
    k_minmax<<<1024, 256>>>(x,    MROWS*DMODEL, 0);
    k_minmax<<<1024, 256>>>(wqkv, J3*DMODEL,    1);
    k_quantrow<<<MROWS, 256>>>(x, p_xq, p_rowsum_x, 0, DMODEL);
    k_quantW<<<J3, 256>>>(wqkv, p_wq1, p_colsum_w1, 1, DMODEL, J3);
    // QKV projection + fused rowsum/region-minmax epilogue
    k_mma<1><<<dim3(J3/128, MROWS/128), 256>>>(
        p_xq, DMODEL, p_wq1, J3, p_xqkv, J3, DMODEL,
        p_colsum_w1, p_rowsum_x, 0, 1, (float)DMODEL, (const float*)0);
    k_pack_qkv<<<dim3(SEQ/4, BHN), 256>>>();
    k_attn_stats<<<dim3(8, BHN), 256>>>();
    k_attn_av<<<dim3(8, BHN), 256>>>();
    k_minmax<<<1024, 256>>>(p_outbuf, MROWS*DMODEL,  6);
    k_minmax<<<1024, 256>>>(wout,     DMODEL*DMODEL, 7);
    k_quantrow<<<MROWS, 256>>>(p_outbuf, p_xq, p_rowsum_x /*dummy*/, 6, DMODEL);
    k_quantW<<<DMODEL, 256>>>(wout, p_wq2, p_colsum_w2, 7, DMODEL, DMODEL);
    // output projection (rowsum uses fused xqkvsum — faithful to ref)
    k_mma<0><<<dim3(DMODEL/128, MROWS/128), 256>>>(
        p_xq, DMODEL, p_wq2, DMODEL, out, DMODEL, DMODEL,
        p_colsum_w2, p_xqkvsum, 6, 7, (float)J3, bout);
}

// round 6
// speedup vs baseline: 6.9321x; 1.2034x over previous
#include <cuda_runtime.h>
#include <cuda_bf16.h>
#include <cstdint>
#include <cstddef>
#include <math.h>

#define NB      4
#define SEQ     1024
#define DMODEL  768
#define NH      12
#define DHD     64
#define J3      2304
#define MROWS   4096          // NB*SEQ
#define BHN     48            // NB*NH

typedef __nv_bfloat16 bf16;
typedef unsigned int  u32;

// ---------------- scratch ----------------
__device__ __align__(16) bf16  g_xq[MROWS*DMODEL];
__device__ __align__(16) bf16  g_wq1[DMODEL*J3];
__device__ __align__(16) bf16  g_wq2[DMODEL*DMODEL];
__device__ __align__(16) float g_xqkv[MROWS*J3];
__device__ __align__(16) bf16  g_qb[BHN*SEQ*DHD];
__device__ __align__(16) bf16  g_kb[BHN*SEQ*DHD];
__device__ __align__(16) bf16  g_vb[BHN*SEQ*DHD];
__device__ __align__(16) float g_outbuf[MROWS*DMODEL];
__device__ float    g_rowsum_x[MROWS];
__device__ float    g_colsum_w1[J3];
__device__ float    g_colsum_w2[DMODEL];
__device__ float    g_xqkvsum[MROWS];
__device__ float    g_rowsumq[BHN*SEQ];
__device__ float    g_colsumk[BHN*SEQ];
__device__ float    g_vcolsum[BHN*DHD];
__device__ float    g_rowm[BHN*SEQ];
__device__ float    g_rowS[BHN*SEQ];
__device__ unsigned g_stat[16];   // slots:0=x 1=w1 2=q 3=k 4=v 5=a 6=out 7=w2

// ---------------- helpers ----------------
__device__ __forceinline__ unsigned fenc(float f){
    unsigned u = __float_as_uint(f);
    return (u & 0x80000000u) ? ~u : (u | 0x80000000u);
}
__device__ __forceinline__ float fdec(unsigned e){
    return (e & 0x80000000u) ? __uint_as_float(e ^ 0x80000000u) : __uint_as_float(~e);
}
__device__ __forceinline__ void get_sz(int slot, float& s, float& z){
    float mx = fdec(g_stat[2*slot]);
    float mn = fdec(g_stat[2*slot+1]);
    s = __fdiv_rn(mx - mn, 15.0f);
    z = rintf(15.0f - __fdiv_rn(mx, s));
}
__device__ __forceinline__ float quant(float v, float s, float z){
    return rintf(__fdiv_rn(v, s) + z);
}
__device__ __forceinline__ u32 packbf2(float lo, float hi){
    __nv_bfloat162 t = __floats2bfloat162_rn(lo, hi);
    return *reinterpret_cast<u32*>(&t);
}
__device__ __forceinline__ void ldsm4(u32* r, const void* p){
    u32 a = (u32)__cvta_generic_to_shared(p);
    asm volatile("ldmatrix.sync.aligned.m8n8.x4.shared.b16 {%0,%1,%2,%3},[%4];"
        : "=r"(r[0]),"=r"(r[1]),"=r"(r[2]),"=r"(r[3]) : "r"(a));
}
__device__ __forceinline__ void ldsm2(u32* r, const void* p){
    u32 a = (u32)__cvta_generic_to_shared(p);
    asm volatile("ldmatrix.sync.aligned.m8n8.x2.shared.b16 {%0,%1},[%2];"
        : "=r"(r[0]),"=r"(r[1]) : "r"(a));
}
__device__ __forceinline__ void ldsm2t(u32* r, const void* p){
    u32 a = (u32)__cvta_generic_to_shared(p);
    asm volatile("ldmatrix.sync.aligned.m8n8.x2.trans.shared.b16 {%0,%1},[%2];"
        : "=r"(r[0]),"=r"(r[1]) : "r"(a));
}
__device__ __forceinline__ void mma16816(float* c, const u32* a, const u32* b){
    asm volatile("mma.sync.aligned.m16n8k16.row.col.f32.bf16.bf16.f32 "
        "{%0,%1,%2,%3}, {%4,%5,%6,%7}, {%8,%9}, {%0,%1,%2,%3};"
        : "+f"(c[0]),"+f"(c[1]),"+f"(c[2]),"+f"(c[3])
        : "r"(a[0]),"r"(a[1]),"r"(a[2]),"r"(a[3]), "r"(b[0]),"r"(b[1]));
}
__device__ __forceinline__ void cpa(void* s, const void* g){
    u32 a = (u32)__cvta_generic_to_shared(s);
    asm volatile("cp.async.cg.shared.global [%0],[%1],16;" :: "r"(a), "l"(g));
}
#define CP_COMMIT asm volatile("cp.async.commit_group;")
#define CP_WAIT0  asm volatile("cp.async.wait_group 0;")
#define CP_WAIT1  asm volatile("cp.async.wait_group 1;")
#define CP_WAIT2  asm volatile("cp.async.wait_group 2;")

__device__ __forceinline__ float qsum(float v){
    v += __shfl_xor_sync(0xffffffffu, v, 1);
    v += __shfl_xor_sync(0xffffffffu, v, 2);
    return v;
}
__device__ __forceinline__ float qmax(float v){
    v = fmaxf(v, __shfl_xor_sync(0xffffffffu, v, 1));
    v = fmaxf(v, __shfl_xor_sync(0xffffffffu, v, 2));
    return v;
}
__device__ __forceinline__ float qmin(float v){
    v = fminf(v, __shfl_xor_sync(0xffffffffu, v, 1));
    v = fminf(v, __shfl_xor_sync(0xffffffffu, v, 2));
    return v;
}
__device__ __forceinline__ float wsum(float v){
    #pragma unroll
    for (int o = 16; o > 0; o >>= 1) v += __shfl_xor_sync(0xffffffffu, v, o);
    return v;
}

// ---------------- elementwise kernels ----------------
__global__ void k_init(){
    int t = threadIdx.x;
    if (t < 8){ g_stat[2*t] = fenc(-INFINITY); g_stat[2*t+1] = fenc(INFINITY); }
    for (int i = t; i < BHN*DHD; i += blockDim.x) g_vcolsum[i] = 0.f;
    for (int i = t; i < MROWS;   i += blockDim.x) g_xqkvsum[i] = 0.f;
    for (int i = t; i < J3;      i += blockDim.x) g_colsum_w1[i] = 0.f;
    for (int i = t; i < DMODEL;  i += blockDim.x) g_colsum_w2[i] = 0.f;
}

__global__ void k_minmax(const float* __restrict__ p, int n, int slot){
    float mx = -INFINITY, mn = INFINITY;
    int n4 = n >> 2;
    const float4* p4 = (const float4*)p;
    for (int i = blockIdx.x*blockDim.x + threadIdx.x; i < n4; i += gridDim.x*blockDim.x){
        float4 v = p4[i];
        mx = fmaxf(mx, fmaxf(fmaxf(v.x,v.y), fmaxf(v.z,v.w)));
        mn = fminf(mn, fminf(fminf(v.x,v.y), fminf(v.z,v.w)));
    }
    __shared__ float smx[256], smn[256];
    int t = threadIdx.x;
    smx[t] = mx; smn[t] = mn; __syncthreads();
    for (int o = 128; o > 0; o >>= 1){
        if (t < o){ smx[t] = fmaxf(smx[t], smx[t+o]); smn[t] = fminf(smn[t], smn[t+o]); }
        __syncthreads();
    }
    if (t == 0){
        atomicMax(&g_stat[2*slot],   fenc(smx[0]));
        atomicMin(&g_stat[2*slot+1], fenc(smn[0]));
    }
}

// warp-per-row quantize -> bf16, fused row sums (rowlen must be 768)
__global__ void k_quantrow(const float* __restrict__ src, bf16* __restrict__ dst,
                           float* __restrict__ rowsum, int slot){
    int warp = threadIdx.x >> 5, lane = threadIdx.x & 31;
    int r = blockIdx.x*8 + warp;
    float s, z; get_sz(slot, s, z);
    const float4* s4 = (const float4*)(src + (long long)r*DMODEL);
    uint2* d2 = (uint2*)(dst + (long long)r*DMODEL);
    float acc = 0.f;
    #pragma unroll
    for (int i = 0; i < 6; i++){
        float4 v = s4[i*32 + lane];
        float q0 = quant(v.x, s, z), q1 = quant(v.y, s, z);
        float q2 = quant(v.z, s, z), q3 = quant(v.w, s, z);
        acc += (q0+q1) + (q2+q3);
        uint2 o; o.x = packbf2(q0,q1); o.y = packbf2(q2,q3);
        d2[i*32 + lane] = o;
    }
    acc = wsum(acc);
    if (lane == 0) rowsum[r] = acc;
}

// quantize weight [Ncols][K] into transposed bf16 wq [K][Ncols] via 32x32 smem tiles.
// colsum over K per column j accumulated with atomics (exact integer sums).
__global__ void k_quantW(const float* __restrict__ w, bf16* __restrict__ wq,
                         float* __restrict__ colsum, int slot, int K, int Ncols){
    __shared__ float tile[32][33];
    int j0 = blockIdx.x*32, d0 = blockIdx.y*32;
    int tid = threadIdx.x;
    float s, z; get_sz(slot, s, z);
    int dd = tid & 31, jb = tid >> 5;
    #pragma unroll
    for (int p = 0; p < 4; p++){
        int jj = jb + p*8;
        tile[jj][dd] = quant(w[(long long)(j0+jj)*K + d0 + dd], s, z);
    }
    __syncthreads();
    if (tid < 32){
        float sum = 0.f;
        #pragma unroll
        for (int k = 0; k < 32; k++) sum += tile[tid][k];
        atomicAdd(&colsum[j0 + tid], sum);
    }
    int jj2 = tid & 31, db = tid >> 5;
    #pragma unroll
    for (int p = 0; p < 4; p++){
        int dd2 = db + p*8;
        wq[(long long)(d0+dd2)*Ncols + j0 + jj2] = __float2bfloat16(tile[jj2][dd2]);
    }
}

// warp-per-token pack of quantized q/k/v; fused token sums + v colsum
__global__ void k_pack_qkv(){
    __shared__ float vsum[64];
    int bh = blockIdx.y;
    int b = bh / NH, h = bh - b*NH;
    int warp = threadIdx.x >> 5, lane = threadIdx.x & 31;
    int n = blockIdx.x*8 + warp;
    if (threadIdx.x < 64) vsum[threadIdx.x] = 0.f;
    __syncthreads();
    float sq, zq, sk, zk, sv, zv;
    get_sz(2, sq, zq); get_sz(3, sk, zk); get_sz(4, sv, zv);
    long long base = (long long)(b*SEQ + n)*J3 + h*DHD + 2*lane;
    float2 qv2 = *(const float2*)&g_xqkv[base];
    float2 kv2 = *(const float2*)&g_xqkv[base + DMODEL];
    float2 vv2 = *(const float2*)&g_xqkv[base + 2*DMODEL];
    float q0 = quant(qv2.x, sq, zq), q1 = quant(qv2.y, sq, zq);
    float k0 = quant(kv2.x, sk, zk), k1 = quant(kv2.y, sk, zk);
    float v0 = quant(vv2.x, sv, zv), v1 = quant(vv2.y, sv, zv);
    long long po = ((long long)bh*SEQ + n)*DHD/2 + lane;   // u32 index
    ((u32*)g_qb)[po] = packbf2(q0, q1);
    ((u32*)g_kb)[po] = packbf2(k0, k1);
    ((u32*)g_vb)[po] = packbf2(v0, v1);
    float qs = wsum(q0 + q1);
    float ks = wsum(k0 + k1);
    if (lane == 0){
        g_rowsumq[bh*SEQ + n] = qs;
        g_colsumk[bh*SEQ + n] = ks;
    }
    atomicAdd(&vsum[2*lane],   v0);
    atomicAdd(&vsum[2*lane+1], v1);
    __syncthreads();
    if (threadIdx.x < 64) atomicAdd(&g_vcolsum[bh*DHD + threadIdx.x], vsum[threadIdx.x]);
}

// ---------------- fused attention: stats pass (cp.async pipelined) ----------------
// dyn smem: Qs[128*72] | Ks[2][128*72] | csk[2][128]
__global__ void __launch_bounds__(256) k_attn_stats(){
    extern __shared__ __align__(16) char smraw[];
    bf16* Qs  = (bf16*)smraw;                       // 18432 B
    bf16* Ks0 = (bf16*)(smraw + 18432);
    bf16* Ks1 = (bf16*)(smraw + 18432*2);
    float* csk0 = (float*)(smraw + 18432*3);
    float* csk1 = (float*)(smraw + 18432*3 + 512);
    __shared__ float redx[256], redn[256];

    int bh = blockIdx.y, qt = blockIdx.x;
    int tid = threadIdx.x, warp = tid >> 5, lane = tid & 31;
    int l16 = lane & 15;

    float sq, zq, sk, zk;
    get_sz(2, sq, zq); get_sz(3, sk, zk);
    float s3 = (0.125f * sq) * sk;

    // prologue: G0 = {K0,csk0}, G1 = {Q}
    {
        #pragma unroll
        for (int it = 0; it < 4; it++){
            int idx = it*256 + tid;
            int r = idx >> 3, c8 = idx & 7;
            cpa(&Ks0[r*72 + c8*8], &g_kb[((long long)bh*SEQ + r)*DHD + c8*8]);
        }
        if (tid < 32) cpa(&csk0[tid*4], &g_colsumk[bh*SEQ + tid*4]);
        CP_COMMIT;
        #pragma unroll
        for (int it = 0; it < 4; it++){
            int idx = it*256 + tid;
            int r = idx >> 3, c8 = idx & 7;
            cpa(&Qs[r*72 + c8*8], &g_qb[((long long)bh*SEQ + qt*128 + r)*DHD + c8*8]);
        }
        CP_COMMIT;
    }

    int r0 = warp*16 + (lane>>2), r1 = r0 + 8;
    float rsq0 = g_rowsumq[bh*SEQ + qt*128 + r0];
    float rsq1 = g_rowsumq[bh*SEQ + qt*128 + r1];

    float m0 = -INFINITY, m1 = -INFINITY;
    float n0 =  INFINITY, n1 =  INFINITY;
    float S0 = 0.f, S1 = 0.f;

    int st = 0;
    for (int kt = 0; kt < 8; kt++){
        bf16*  Kc  = st ? Ks1 : Ks0;
        float* ckc = st ? csk1 : csk0;
        if (kt < 7){
            bf16*  Kn  = st ? Ks0 : Ks1;
            float* ckn = st ? csk0 : csk1;
            #pragma unroll
            for (int it = 0; it < 4; it++){
                int idx = it*256 + tid;
                int r = idx >> 3, c8 = idx & 7;
                cpa(&Kn[r*72 + c8*8], &g_kb[((long long)bh*SEQ + (kt+1)*128 + r)*DHD + c8*8]);
            }
            if (tid < 32) cpa(&ckn[tid*4], &g_colsumk[bh*SEQ + (kt+1)*128 + tid*4]);
            CP_COMMIT;
            CP_WAIT1;
        } else {
            CP_WAIT0;
        }
        __syncthreads();

        float acc[16][4];
        #pragma unroll
        for (int nt = 0; nt < 16; nt++){ acc[nt][0]=0.f; acc[nt][1]=0.f; acc[nt][2]=0.f; acc[nt][3]=0.f; }
        #pragma unroll
        for (int kk = 0; kk < 64; kk += 16){
            u32 af[4];
            ldsm4(af, &Qs[(warp*16 + l16)*72 + kk + (lane>>4)*8]);
            #pragma unroll
            for (int nt = 0; nt < 16; nt++){
                u32 bf[2];
                ldsm2(bf, &Kc[(nt*8 + (l16&7))*72 + kk + ((l16>>3)&1)*8]);
                mma16816(acc[nt], af, bf);
            }
        }

        int c = (lane&3)*2;
        #pragma unroll
        for (int nt = 0; nt < 16; nt++){
            int cg = nt*8 + c;
            float cz0 = ckc[cg]*zq, cz1 = ckc[cg+1]*zq;
            acc[nt][0] = (acc[nt][0] - cz0 - rsq0*zk)*s3;
            acc[nt][1] = (acc[nt][1] - cz1 - rsq0*zk)*s3;
            acc[nt][2] = (acc[nt][2] - cz0 - rsq1*zk)*s3;
            acc[nt][3] = (acc[nt][3] - cz1 - rsq1*zk)*s3;
        }
        float tx0=-INFINITY, tx1=-INFINITY, tn0=INFINITY, tn1=INFINITY;
        #pragma unroll
        for (int nt = 0; nt < 16; nt++){
            tx0 = fmaxf(tx0, fmaxf(acc[nt][0], acc[nt][1]));
            tx1 = fmaxf(tx1, fmaxf(acc[nt][2], acc[nt][3]));
            tn0 = fminf(tn0, fminf(acc[nt][0], acc[nt][1]));
            tn1 = fminf(tn1, fminf(acc[nt][2], acc[nt][3]));
        }
        tx0 = qmax(tx0); tx1 = qmax(tx1);
        tn0 = qmin(tn0); tn1 = qmin(tn1);
        float nm0 = fmaxf(m0, tx0), nm1 = fmaxf(m1, tx1);
        float se0 = 0.f, se1 = 0.f;
        #pragma unroll
        for (int nt = 0; nt < 16; nt++){
            se0 += expf(acc[nt][0]-nm0) + expf(acc[nt][1]-nm0);
            se1 += expf(acc[nt][2]-nm1) + expf(acc[nt][3]-nm1);
        }
        se0 = qsum(se0); se1 = qsum(se1);
        S0 = S0*expf(m0-nm0) + se0;  m0 = nm0;  n0 = fminf(n0, tn0);
        S1 = S1*expf(m1-nm1) + se1;  m1 = nm1;  n1 = fminf(n1, tn1);

        __syncthreads();
        st ^= 1;
    }

    if ((lane & 3) == 0){
        g_rowm[bh*SEQ + qt*128 + r0] = m0;  g_rowS[bh*SEQ + qt*128 + r0] = S0;
        g_rowm[bh*SEQ + qt*128 + r1] = m1;  g_rowS[bh*SEQ + qt*128 + r1] = S1;
    }
    float ax = fmaxf(__fdiv_rn(1.0f, S0), __fdiv_rn(1.0f, S1));
    float an = fminf(__fdiv_rn(expf(n0 - m0), S0), __fdiv_rn(expf(n1 - m1), S1));
    redx[tid] = ax; redn[tid] = an; __syncthreads();
    for (int o = 128; o > 0; o >>= 1){
        if (tid < o){ redx[tid] = fmaxf(redx[tid], redx[tid+o]); redn[tid] = fminf(redn[tid], redn[tid+o]); }
        __syncthreads();
    }
    if (tid == 0){
        atomicMax(&g_stat[10], fenc(redx[0]));
        atomicMin(&g_stat[11], fenc(redn[0]));
    }
}

// ---------------- fused attention: recompute + quantize + AV (cp.async pipelined) ----------------
// dyn smem: Qs | Ks[2] | Vs | csk[2] | vcs
__global__ void __launch_bounds__(256) k_attn_av(){
    extern __shared__ __align__(16) char smraw[];
    bf16* Qs  = (bf16*)smraw;
    bf16* Ks0 = (bf16*)(smraw + 18432);
    bf16* Ks1 = (bf16*)(smraw + 18432*2);
    bf16* Vs  = (bf16*)(smraw + 18432*3);
    float* csk0 = (float*)(smraw + 18432*4);
    float* csk1 = (float*)(smraw + 18432*4 + 512);
    float* vcs  = (float*)(smraw + 18432*4 + 1024);

    int bh = blockIdx.y, qt = blockIdx.x;
    int b = bh / NH, h = bh - b*NH;
    int tid = threadIdx.x, warp = tid >> 5, lane = tid & 31;
    int l16 = lane & 15;

    float sq, zq, sk, zk, sv, zv, sa, za;
    get_sz(2, sq, zq); get_sz(3, sk, zk); get_sz(4, sv, zv); get_sz(5, sa, za);
    float s3 = (0.125f * sq) * sk;

    // prologue: G0 = {K0,csk0}, G1 = {Q,vcs}
    {
        #pragma unroll
        for (int it = 0; it < 4; it++){
            int idx = it*256 + tid;
            int r = idx >> 3, c8 = idx & 7;
            cpa(&Ks0[r*72 + c8*8], &g_kb[((long long)bh*SEQ + r)*DHD + c8*8]);
        }
        if (tid < 32) cpa(&csk0[tid*4], &g_colsumk[bh*SEQ + tid*4]);
        CP_COMMIT;
        #pragma unroll
        for (int it = 0; it < 4; it++){
            int idx = it*256 + tid;
            int r = idx >> 3, c8 = idx & 7;
            cpa(&Qs[r*72 + c8*8], &g_qb[((long long)bh*SEQ + qt*128 + r)*DHD + c8*8]);
        }
        if (tid < 16) cpa(&vcs[tid*4], &g_vcolsum[bh*DHD + tid*4]);
        CP_COMMIT;
    }

    int r0 = warp*16 + (lane>>2), r1 = r0 + 8;
    float rsq0 = g_rowsumq[bh*SEQ + qt*128 + r0];
    float rsq1 = g_rowsumq[bh*SEQ + qt*128 + r1];
    float m0 = g_rowm[bh*SEQ + qt*128 + r0], S0 = g_rowS[bh*SEQ + qt*128 + r0];
    float m1 = g_rowm[bh*SEQ + qt*128 + r1], S1 = g_rowS[bh*SEQ + qt*128 + r1];

    float oacc[8][4];
    #pragma unroll
    for (int nt = 0; nt < 8; nt++){ oacc[nt][0]=0.f; oacc[nt][1]=0.f; oacc[nt][2]=0.f; oacc[nt][3]=0.f; }
    float aqs0 = 0.f, aqs1 = 0.f;

    int st = 0;
    for (int kt = 0; kt < 8; kt++){
        bf16*  Kc  = st ? Ks1 : Ks0;
        float* ckc = st ? csk1 : csk0;
        if (kt < 7){
            bf16*  Kn  = st ? Ks0 : Ks1;
            float* ckn = st ? csk0 : csk1;
            #pragma unroll
            for (int it = 0; it < 4; it++){
                int idx = it*256 + tid;
                int r = idx >> 3, c8 = idx & 7;
                cpa(&Kn[r*72 + c8*8], &g_kb[((long long)bh*SEQ + (kt+1)*128 + r)*DHD + c8*8]);
            }
            if (tid < 32) cpa(&ckn[tid*4], &g_colsumk[bh*SEQ + (kt+1)*128 + tid*4]);
            CP_COMMIT;
        }
        // V(kt) into single V buffer (prev readers finished at end-of-iter barrier)
        #pragma unroll
        for (int it = 0; it < 4; it++){
            int idx = it*256 + tid;
            int r = idx >> 3, c8 = idx & 7;
            cpa(&Vs[r*72 + c8*8], &g_vb[((long long)bh*SEQ + kt*128 + r)*DHD + c8*8]);
        }
        CP_COMMIT;
        if (kt < 7) { CP_WAIT2; } else { CP_WAIT1; }   // K(kt)+csk ready (and Q on kt=0)
        __syncthreads();

        float acc[16][4];
        #pragma unroll
        for (int nt = 0; nt < 16; nt++){ acc[nt][0]=0.f; acc[nt][1]=0.f; acc[nt][2]=0.f; acc[nt][3]=0.f; }
        #pragma unroll
        for (int kk = 0; kk < 64; kk += 16){
            u32 af[4];
            ldsm4(af, &Qs[(warp*16 + l16)*72 + kk + (lane>>4)*8]);
            #pragma unroll
            for (int nt = 0; nt < 16; nt++){
                u32 bf[2];
                ldsm2(bf, &Kc[(nt*8 + (l16&7))*72 + kk + ((l16>>3)&1)*8]);
                mma16816(acc[nt], af, bf);
            }
        }

        int c = (lane&3)*2;
        #pragma unroll
        for (int nt = 0; nt < 16; nt++){
            int cg = nt*8 + c;
            float cz0 = ckc[cg]*zq, cz1 = ckc[cg+1]*zq;
            acc[nt][0] = (acc[nt][0] - cz0 - rsq0*zk)*s3;
            acc[nt][1] = (acc[nt][1] - cz1 - rsq0*zk)*s3;
            acc[nt][2] = (acc[nt][2] - cz0 - rsq1*zk)*s3;
            acc[nt][3] = (acc[nt][3] - cz1 - rsq1*zk)*s3;
        }

        if (kt < 7) { CP_WAIT1; } else { CP_WAIT0; }   // V(kt) ready
        __syncthreads();

        #pragma unroll
        for (int j = 0; j < 8; j++){
            float q00, q01, q02, q03, q10, q11, q12, q13;
            {
                float a0 = __fdiv_rn(expf(acc[2*j][0]   - m0), S0);
                float a1 = __fdiv_rn(expf(acc[2*j][1]   - m0), S0);
                float a2 = __fdiv_rn(expf(acc[2*j][2]   - m1), S1);
                float a3 = __fdiv_rn(expf(acc[2*j][3]   - m1), S1);
                q00 = quant(a0, sa, za); q01 = quant(a1, sa, za);
                q02 = quant(a2, sa, za); q03 = quant(a3, sa, za);
                float b0 = __fdiv_rn(expf(acc[2*j+1][0] - m0), S0);
                float b1 = __fdiv_rn(expf(acc[2*j+1][1] - m0), S0);
                float b2 = __fdiv_rn(expf(acc[2*j+1][2] - m1), S1);
                float b3 = __fdiv_rn(expf(acc[2*j+1][3] - m1), S1);
                q10 = quant(b0, sa, za); q11 = quant(b1, sa, za);
                q12 = quant(b2, sa, za); q13 = quant(b3, sa, za);
            }
            aqs0 += q00 + q01 + q10 + q11;
            aqs1 += q02 + q03 + q12 + q13;
            u32 pa[4];
            pa[0] = packbf2(q00, q01);
            pa[1] = packbf2(q02, q03);
            pa[2] = packbf2(q10, q11);
            pa[3] = packbf2(q12, q13);
            #pragma unroll
            for (int nt = 0; nt < 8; nt++){
                u32 vf[2];
                ldsm2t(vf, &Vs[(16*j + l16)*72 + nt*8]);
                mma16816(oacc[nt], pa, vf);
            }
        }
        __syncthreads();   // all done reading Ks[st], Vs before next iter's cp.async
        st ^= 1;
    }

    aqs0 = qsum(aqs0);
    aqs1 = qsum(aqs1);

    float mult  = sa * sv;
    float cterm = (za * zv) * (float)SEQ;
    int c = (lane&3)*2;
    long long ob0 = (long long)(b*SEQ + qt*128 + r0)*DMODEL + h*DHD;
    long long ob1 = (long long)(b*SEQ + qt*128 + r1)*DMODEL + h*DHD;
    #pragma unroll
    for (int nt = 0; nt < 8; nt++){
        int d0 = nt*8 + c;
        float w0 = vcs[d0]*za, w1 = vcs[d0+1]*za;
        g_outbuf[ob0 + d0]     = (oacc[nt][0] - w0 - aqs0*zv + cterm)*mult;
        g_outbuf[ob0 + d0 + 1] = (oacc[nt][1] - w1 - aqs0*zv + cterm)*mult;
        g_outbuf[ob1 + d0]     = (oacc[nt][2] - w0 - aqs1*zv + cterm)*mult;
        g_outbuf[ob1 + d0 + 1] = (oacc[nt][3] - w1 - aqs1*zv + cterm)*mult;
    }
}

// ---------------- pipelined tensor-core GEMM with affine epilogue ----------------
template<int F1>
__global__ void __launch_bounds__(256) k_mma(
    const bf16* __restrict__ A, int lda,
    const bf16* __restrict__ Bm, int ldb,
    float* __restrict__ C, int ldc,
    int K,
    const float* __restrict__ colsumB,
    const float* __restrict__ rowsumA,
    int slotA, int slotB, float Kconst,
    const float* __restrict__ bias)
{
    const int BK = 32, APAD = 40, BPAD = 136;
    __shared__ __align__(16) bf16 As[2][128*APAD];
    __shared__ __align__(16) bf16 Bs[2][BK*BPAD];
    __shared__ float redx[256], redn[256];

    int i0 = blockIdx.y * 128, j0 = blockIdx.x * 128;
    int tid = threadIdx.x, warp = tid >> 5, lane = tid & 31;
    int wm = warp >> 2, wn = warp & 3;
    int l16 = lane & 15;

    float acc[4][4][4];
    #pragma unroll
    for (int a = 0; a < 4; a++)
        #pragma unroll
        for (int b = 0; b < 4; b++){
            acc[a][b][0]=0.f; acc[a][b][1]=0.f; acc[a][b][2]=0.f; acc[a][b][3]=0.f;
        }

    // prologue load
    {
        #pragma unroll
        for (int v = 0; v < 2; v++){
            int idx = v*256 + tid;
            int r = idx >> 2, c8 = idx & 3;
            cpa(&As[0][r*APAD + c8*8], &A[(long long)(i0 + r)*lda + c8*8]);
        }
        #pragma unroll
        for (int v = 0; v < 2; v++){
            int idx = v*256 + tid;
            int r = idx >> 4, c8 = idx & 15;
            cpa(&Bs[0][r*BPAD + c8*8], &Bm[(long long)r*ldb + j0 + c8*8]);
        }
        CP_COMMIT;
    }

    int st = 0;
    for (int k0 = 0; k0 < K; k0 += BK){
        if (k0 + BK < K){
            int ns = st ^ 1, kn = k0 + BK;
            #pragma unroll
            for (int v = 0; v < 2; v++){
                int idx = v*256 + tid;
                int r = idx >> 2, c8 = idx & 3;
                cpa(&As[ns][r*APAD + c8*8], &A[(long long)(i0 + r)*lda + kn + c8*8]);
            }
            #pragma unroll
            for (int v = 0; v < 2; v++){
                int idx = v*256 + tid;
                int r = idx >> 4, c8 = idx & 15;
                cpa(&Bs[ns][r*BPAD + c8*8], &Bm[(long long)(kn + r)*ldb + j0 + c8*8]);
            }
            CP_COMMIT;
            CP_WAIT1;
        } else {
            CP_WAIT0;
        }
        __syncthreads();

        #pragma unroll
        for (int kk = 0; kk < BK; kk += 16){
            u32 af[4][4];
            #pragma unroll
            for (int mt = 0; mt < 4; mt++)
                ldsm4(af[mt], &As[st][(wm*64 + mt*16 + l16)*APAD + kk + (lane>>4)*8]);
            u32 bf[4][2];
            #pragma unroll
            for (int nt = 0; nt < 4; nt++)
                ldsm2t(bf[nt], &Bs[st][(kk + l16)*BPAD + wn*32 + nt*8]);
            #pragma unroll
            for (int mt = 0; mt < 4; mt++)
                #pragma unroll
                for (int nt = 0; nt < 4; nt++)
                    mma16816(acc[mt][nt], af[mt], bf[nt]);
        }
        __syncthreads();
        st ^= 1;
    }

    float sA, zA, sB, zB;
    get_sz(slotA, sA, zA); get_sz(slotB, sB, zB);
    float mult  = sA * sB;
    float cterm = (zA * zB) * Kconst;

    float lmx = -INFINITY, lmn = INFINITY;

    #pragma unroll
    for (int mt = 0; mt < 4; mt++){
        int row0 = i0 + wm*64 + mt*16 + (lane>>2);
        float rs0 = rowsumA[row0], rs1 = rowsumA[row0+8];
        float p0 = 0.f, p8 = 0.f;
        #pragma unroll
        for (int nt = 0; nt < 4; nt++){
            int col0 = j0 + wn*32 + nt*8 + (lane&3)*2;
            float cs0 = colsumB[col0], cs1 = colsumB[col0+1];
            float b0 = bias ? bias[col0]   : 0.f;
            float b1 = bias ? bias[col0+1] : 0.f;
            float v0 = (acc[mt][nt][0] - cs0*zA - rs0*zB + cterm)*mult + b0;
            float v1 = (acc[mt][nt][1] - cs1*zA - rs0*zB + cterm)*mult + b1;
            float v2 = (acc[mt][nt][2] - cs0*zA - rs1*zB + cterm)*mult + b0;
            float v3 = (acc[mt][nt][3] - cs1*zA - rs1*zB + cterm)*mult + b1;
            C[(long long)row0*ldc + col0]       = v0;
            C[(long long)row0*ldc + col0 + 1]   = v1;
            C[(long long)(row0+8)*ldc + col0]   = v2;
            C[(long long)(row0+8)*ldc + col0+1] = v3;
            if (F1){
                p0 += v0 + v1; p8 += v2 + v3;
                lmx = fmaxf(lmx, fmaxf(fmaxf(v0,v1), fmaxf(v2,v3)));
                lmn = fminf(lmn, fminf(fminf(v0,v1), fminf(v2,v3)));
            }
        }
        if (F1){
            p0 = qsum(p0); p8 = qsum(p8);
            if ((lane & 3) == 0){
                atomicAdd(&g_xqkvsum[row0],   p0);
                atomicAdd(&g_xqkvsum[row0+8], p8);
            }
        }
    }

    if (F1){
        redx[tid] = lmx; redn[tid] = lmn; __syncthreads();
        for (int o = 128; o > 0; o >>= 1){
            if (tid < o){ redx[tid] = fmaxf(redx[tid], redx[tid+o]); redn[tid] = fminf(redn[tid], redn[tid+o]); }
            __syncthreads();
        }
        if (tid == 0){
            int region = blockIdx.x / 6;
            atomicMax(&g_stat[2*(2+region)],   fenc(redx[0]));
            atomicMin(&g_stat[2*(2+region)+1], fenc(redn[0]));
        }
    }
}

// ---------------- launcher ----------------
extern "C" void kernel_launch(void* const* d_in, const int* in_sizes, int n_in,
                              void* d_out, int out_size){
    const float *x = 0, *wqkv = 0, *wout = 0, *bout = 0;
    for (int i = 0; i < n_in; i++){
        if      (in_sizes[i] == MROWS*DMODEL)  x    = (const float*)d_in[i];
        else if (in_sizes[i] == J3*DMODEL)     wqkv = (const float*)d_in[i];
        else if (in_sizes[i] == DMODEL*DMODEL) wout = (const float*)d_in[i];
        else if (in_sizes[i] == DMODEL)        bout = (const float*)d_in[i];
    }
    float* out = (float*)d_out;

    bf16 *p_xq, *p_wq1, *p_wq2;
    float *p_xqkv, *p_outbuf;
    float *p_rowsum_x, *p_colsum_w1, *p_colsum_w2, *p_xqkvsum;
    cudaGetSymbolAddress((void**)&p_xq,        g_xq);
    cudaGetSymbolAddress((void**)&p_wq1,       g_wq1);
    cudaGetSymbolAddress((void**)&p_wq2,       g_wq2);
    cudaGetSymbolAddress((void**)&p_xqkv,      g_xqkv);
    cudaGetSymbolAddress((void**)&p_outbuf,    g_outbuf);
    cudaGetSymbolAddress((void**)&p_rowsum_x,  g_rowsum_x);
    cudaGetSymbolAddress((void**)&p_colsum_w1, g_colsum_w1);
    cudaGetSymbolAddress((void**)&p_colsum_w2, g_colsum_w2);
    cudaGetSymbolAddress((void**)&p_xqkvsum,   g_xqkvsum);

    static int smem_set = 0;
    if (!smem_set){
        cudaFuncSetAttribute(k_attn_stats, cudaFuncAttributeMaxDynamicSharedMemorySize, 18432*3 + 2048);
        cudaFuncSetAttribute(k_attn_av,    cudaFuncAttributeMaxDynamicSharedMemorySize, 18432*4 + 2048);
        smem_set = 1;
    }

    k_init<<<1, 256>>>();
    k_minmax<<<1024, 256>>>(x,    MROWS*DMODEL, 0);
    k_minmax<<<1024, 256>>>(wqkv, J3*DMODEL,    1);
    k_quantrow<<<MROWS/8, 256>>>(x, p_xq, p_rowsum_x, 0);
    k_quantW<<<dim3(J3/32, DMODEL/32), 256>>>(wqkv, p_wq1, p_colsum_w1, 1, DMODEL, J3);
    k_mma<1><<<dim3(J3/128, MROWS/128), 256>>>(
        p_xq, DMODEL, p_wq1, J3, p_xqkv, J3, DMODEL,
        p_colsum_w1, p_rowsum_x, 0, 1, (float)DMODEL, (const float*)0);
    k_pack_qkv<<<dim3(SEQ/8, BHN), 256>>>();
    k_attn_stats<<<dim3(8, BHN), 256, 18432*3 + 2048>>>();
    k_attn_av<<<dim3(8, BHN), 256, 18432*4 + 2048>>>();
    k_minmax<<<1024, 256>>>(p_outbuf, MROWS*DMODEL,  6);
    k_minmax<<<1024, 256>>>(wout,     DMODEL*DMODEL, 7);
    k_quantrow<<<MROWS/8, 256>>>(p_outbuf, p_xq, p_rowsum_x /*dummy*/, 6);
    k_quantW<<<dim3(DMODEL/32, DMODEL/32), 256>>>(wout, p_wq2, p_colsum_w2, 7, DMODEL, DMODEL);
    k_mma<0><<<dim3(DMODEL/128, MROWS/128), 256>>>(
        p_xq, DMODEL, p_wq2, DMODEL, out, DMODEL, DMODEL,
        p_colsum_w2, p_xqkvsum, 6, 7, (float)J3, bout);
}

// round 7
// speedup vs baseline: 10.6253x; 1.5328x over previous
#include <cuda_runtime.h>
#include <cuda_bf16.h>
#include <cstdint>
#include <cstddef>
#include <math.h>

#define NB      4
#define SEQ     1024
#define DMODEL  768
#define NH      12
#define DHD     64
#define J3      2304
#define MROWS   4096
#define BHN     48

typedef __nv_bfloat16 bf16;
typedef unsigned int  u32;

// ---------------- scratch ----------------
__device__ __align__(16) bf16  g_xq[MROWS*DMODEL];
__device__ __align__(16) bf16  g_wq1[DMODEL*J3];
__device__ __align__(16) bf16  g_wq2[DMODEL*DMODEL];
__device__ __align__(16) float g_xqkv[MROWS*J3];
__device__ __align__(16) bf16  g_qb[BHN*SEQ*DHD];
__device__ __align__(16) bf16  g_kb[BHN*SEQ*DHD];
__device__ __align__(16) bf16  g_vb[BHN*SEQ*DHD];
__device__ __align__(16) float g_outbuf[MROWS*DMODEL];
__device__ float    g_rowsum_x[MROWS];
__device__ float    g_colsum_w1[J3];
__device__ float    g_colsum_w2[DMODEL];
__device__ float    g_xqkvsum[MROWS];
__device__ float    g_rowsumq[BHN*SEQ];
__device__ float    g_colsumk[BHN*SEQ];
__device__ float    g_vcolsum[BHN*DHD];
__device__ float    g_rowm[BHN*SEQ];
__device__ float    g_rowS[BHN*SEQ];
__device__ unsigned g_stat[16];   // slots:0=x 1=w1 2=q 3=k 4=v 5=a 6=out 7=w2

// ---------------- helpers ----------------
__device__ __forceinline__ unsigned fenc(float f){
    unsigned u = __float_as_uint(f);
    return (u & 0x80000000u) ? ~u : (u | 0x80000000u);
}
__device__ __forceinline__ float fdec(unsigned e){
    return (e & 0x80000000u) ? __uint_as_float(e ^ 0x80000000u) : __uint_as_float(~e);
}
// s, z, and inv_s for fast quant
__device__ __forceinline__ void get_szi(int slot, float& s, float& z, float& is){
    float mx = fdec(g_stat[2*slot]);
    float mn = fdec(g_stat[2*slot+1]);
    s = __fdiv_rn(mx - mn, 15.0f);
    z = rintf(15.0f - __fdiv_rn(mx, s));
    is = __fdiv_rn(1.0f, s);
}
__device__ __forceinline__ float quantm(float v, float is, float z){
    return rintf(fmaf(v, is, z));
}
__device__ __forceinline__ u32 packbf2(float lo, float hi){
    __nv_bfloat162 t = __floats2bfloat162_rn(lo, hi);
    return *reinterpret_cast<u32*>(&t);
}
__device__ __forceinline__ void ldsm4(u32* r, const void* p){
    u32 a = (u32)__cvta_generic_to_shared(p);
    asm volatile("ldmatrix.sync.aligned.m8n8.x4.shared.b16 {%0,%1,%2,%3},[%4];"
        : "=r"(r[0]),"=r"(r[1]),"=r"(r[2]),"=r"(r[3]) : "r"(a));
}
__device__ __forceinline__ void ldsm2(u32* r, const void* p){
    u32 a = (u32)__cvta_generic_to_shared(p);
    asm volatile("ldmatrix.sync.aligned.m8n8.x2.shared.b16 {%0,%1},[%2];"
        : "=r"(r[0]),"=r"(r[1]) : "r"(a));
}
__device__ __forceinline__ void ldsm2t(u32* r, const void* p){
    u32 a = (u32)__cvta_generic_to_shared(p);
    asm volatile("ldmatrix.sync.aligned.m8n8.x2.trans.shared.b16 {%0,%1},[%2];"
        : "=r"(r[0]),"=r"(r[1]) : "r"(a));
}
__device__ __forceinline__ void mma16816(float* c, const u32* a, const u32* b){
    asm volatile("mma.sync.aligned.m16n8k16.row.col.f32.bf16.bf16.f32 "
        "{%0,%1,%2,%3}, {%4,%5,%6,%7}, {%8,%9}, {%0,%1,%2,%3};"
        : "+f"(c[0]),"+f"(c[1]),"+f"(c[2]),"+f"(c[3])
        : "r"(a[0]),"r"(a[1]),"r"(a[2]),"r"(a[3]), "r"(b[0]),"r"(b[1]));
}
__device__ __forceinline__ void cpa(void* s, const void* g){
    u32 a = (u32)__cvta_generic_to_shared(s);
    asm volatile("cp.async.cg.shared.global [%0],[%1],16;" :: "r"(a), "l"(g));
}
#define CP_COMMIT asm volatile("cp.async.commit_group;")
#define CP_WAIT0  asm volatile("cp.async.wait_group 0;")
#define CP_WAIT1  asm volatile("cp.async.wait_group 1;")
#define CP_WAIT2  asm volatile("cp.async.wait_group 2;")

__device__ __forceinline__ float qsum(float v){
    v += __shfl_xor_sync(0xffffffffu, v, 1);
    v += __shfl_xor_sync(0xffffffffu, v, 2);
    return v;
}
__device__ __forceinline__ float qmax(float v){
    v = fmaxf(v, __shfl_xor_sync(0xffffffffu, v, 1));
    v = fmaxf(v, __shfl_xor_sync(0xffffffffu, v, 2));
    return v;
}
__device__ __forceinline__ float qmin(float v){
    v = fminf(v, __shfl_xor_sync(0xffffffffu, v, 1));
    v = fminf(v, __shfl_xor_sync(0xffffffffu, v, 2));
    return v;
}
__device__ __forceinline__ float wsum(float v){
    #pragma unroll
    for (int o = 16; o > 0; o >>= 1) v += __shfl_xor_sync(0xffffffffu, v, o);
    return v;
}

// ---------------- elementwise kernels ----------------
__global__ void k_init(){
    int t = threadIdx.x;
    if (t < 8){ g_stat[2*t] = fenc(-INFINITY); g_stat[2*t+1] = fenc(INFINITY); }
    for (int i = t; i < BHN*DHD; i += blockDim.x) g_vcolsum[i] = 0.f;
    for (int i = t; i < MROWS;   i += blockDim.x) g_xqkvsum[i] = 0.f;
    for (int i = t; i < J3;      i += blockDim.x) g_colsum_w1[i] = 0.f;
    for (int i = t; i < DMODEL;  i += blockDim.x) g_colsum_w2[i] = 0.f;
}

// dual-tensor minmax: blockIdx.y selects (p,n,slot)
__global__ void k_minmax2(const float* __restrict__ pa, int na, int sa_,
                          const float* __restrict__ pb, int nb, int sb_){
    const float* p = blockIdx.y ? pb : pa;
    int n    = blockIdx.y ? nb : na;
    int slot = blockIdx.y ? sb_ : sa_;
    float mx = -INFINITY, mn = INFINITY;
    int n4 = n >> 2;
    const float4* p4 = (const float4*)p;
    for (int i = blockIdx.x*blockDim.x + threadIdx.x; i < n4; i += gridDim.x*blockDim.x){
        float4 v = p4[i];
        mx = fmaxf(mx, fmaxf(fmaxf(v.x,v.y), fmaxf(v.z,v.w)));
        mn = fminf(mn, fminf(fminf(v.x,v.y), fminf(v.z,v.w)));
    }
    __shared__ float smx[256], smn[256];
    int t = threadIdx.x;
    smx[t] = mx; smn[t] = mn; __syncthreads();
    for (int o = 128; o > 0; o >>= 1){
        if (t < o){ smx[t] = fmaxf(smx[t], smx[t+o]); smn[t] = fminf(smn[t], smn[t+o]); }
        __syncthreads();
    }
    if (t == 0){
        atomicMax(&g_stat[2*slot],   fenc(smx[0]));
        atomicMin(&g_stat[2*slot+1], fenc(smn[0]));
    }
}

// warp-per-row quantize -> bf16, fused row sums (rowlen 768)
__global__ void k_quantrow(const float* __restrict__ src, bf16* __restrict__ dst,
                           float* __restrict__ rowsum, int slot){
    int warp = threadIdx.x >> 5, lane = threadIdx.x & 31;
    int r = blockIdx.x*8 + warp;
    float s, z, is; get_szi(slot, s, z, is);
    const float4* s4 = (const float4*)(src + (long long)r*DMODEL);
    uint2* d2 = (uint2*)(dst + (long long)r*DMODEL);
    float acc = 0.f;
    #pragma unroll
    for (int i = 0; i < 6; i++){
        float4 v = s4[i*32 + lane];
        float q0 = quantm(v.x, is, z), q1 = quantm(v.y, is, z);
        float q2 = quantm(v.z, is, z), q3 = quantm(v.w, is, z);
        acc += (q0+q1) + (q2+q3);
        uint2 o; o.x = packbf2(q0,q1); o.y = packbf2(q2,q3);
        d2[i*32 + lane] = o;
    }
    acc = wsum(acc);
    if (lane == 0) rowsum[r] = acc;
}

// quantize weight [Ncols][K] -> transposed bf16 [K][Ncols] via 32x32 tiles + colsum atomics
__global__ void k_quantW(const float* __restrict__ w, bf16* __restrict__ wq,
                         float* __restrict__ colsum, int slot, int K, int Ncols){
    __shared__ float tile[32][33];
    int j0 = blockIdx.x*32, d0 = blockIdx.y*32;
    int tid = threadIdx.x;
    float s, z, is; get_szi(slot, s, z, is);
    int dd = tid & 31, jb = tid >> 5;
    #pragma unroll
    for (int p = 0; p < 4; p++){
        int jj = jb + p*8;
        tile[jj][dd] = quantm(w[(long long)(j0+jj)*K + d0 + dd], is, z);
    }
    __syncthreads();
    if (tid < 32){
        float sum = 0.f;
        #pragma unroll
        for (int k = 0; k < 32; k++) sum += tile[tid][k];
        atomicAdd(&colsum[j0 + tid], sum);
    }
    int jj2 = tid & 31, db = tid >> 5;
    #pragma unroll
    for (int p = 0; p < 4; p++){
        int dd2 = db + p*8;
        wq[(long long)(d0+dd2)*Ncols + j0 + jj2] = __float2bfloat16(tile[jj2][dd2]);
    }
}

// warp-per-token pack of quantized q/k/v; fused token sums + v colsum
__global__ void k_pack_qkv(){
    __shared__ float vsum[64];
    int bh = blockIdx.y;
    int b = bh / NH, h = bh - b*NH;
    int warp = threadIdx.x >> 5, lane = threadIdx.x & 31;
    int n = blockIdx.x*8 + warp;
    if (threadIdx.x < 64) vsum[threadIdx.x] = 0.f;
    __syncthreads();
    float sq, zq, iq, sk, zk, ik, sv, zv, iv;
    get_szi(2, sq, zq, iq); get_szi(3, sk, zk, ik); get_szi(4, sv, zv, iv);
    long long base = (long long)(b*SEQ + n)*J3 + h*DHD + 2*lane;
    float2 qv2 = *(const float2*)&g_xqkv[base];
    float2 kv2 = *(const float2*)&g_xqkv[base + DMODEL];
    float2 vv2 = *(const float2*)&g_xqkv[base + 2*DMODEL];
    float q0 = quantm(qv2.x, iq, zq), q1 = quantm(qv2.y, iq, zq);
    float k0 = quantm(kv2.x, ik, zk), k1 = quantm(kv2.y, ik, zk);
    float v0 = quantm(vv2.x, iv, zv), v1 = quantm(vv2.y, iv, zv);
    long long po = ((long long)bh*SEQ + n)*DHD/2 + lane;
    ((u32*)g_qb)[po] = packbf2(q0, q1);
    ((u32*)g_kb)[po] = packbf2(k0, k1);
    ((u32*)g_vb)[po] = packbf2(v0, v1);
    float qs = wsum(q0 + q1);
    float ks = wsum(k0 + k1);
    if (lane == 0){
        g_rowsumq[bh*SEQ + n] = qs;
        g_colsumk[bh*SEQ + n] = ks;
    }
    atomicAdd(&vsum[2*lane],   v0);
    atomicAdd(&vsum[2*lane+1], v1);
    __syncthreads();
    if (threadIdx.x < 64) atomicAdd(&g_vcolsum[bh*DHD + threadIdx.x], vsum[threadIdx.x]);
}

// ---------------- fused attention: stats pass ----------------
__global__ void __launch_bounds__(256) k_attn_stats(){
    extern __shared__ __align__(16) char smraw[];
    bf16* Qs  = (bf16*)smraw;
    bf16* Ks0 = (bf16*)(smraw + 18432);
    bf16* Ks1 = (bf16*)(smraw + 18432*2);
    float* csk0 = (float*)(smraw + 18432*3);
    float* csk1 = (float*)(smraw + 18432*3 + 512);
    __shared__ float redx[256], redn[256];

    int bh = blockIdx.y, qt = blockIdx.x;
    int tid = threadIdx.x, warp = tid >> 5, lane = tid & 31;
    int l16 = lane & 15;

    float sq, zq, iq, sk, zk, ik;
    get_szi(2, sq, zq, iq); get_szi(3, sk, zk, ik);
    float s3 = (0.125f * sq) * sk;

    {
        #pragma unroll
        for (int it = 0; it < 4; it++){
            int idx = it*256 + tid;
            int r = idx >> 3, c8 = idx & 7;
            cpa(&Ks0[r*72 + c8*8], &g_kb[((long long)bh*SEQ + r)*DHD + c8*8]);
        }
        if (tid < 32) cpa(&csk0[tid*4], &g_colsumk[bh*SEQ + tid*4]);
        CP_COMMIT;
        #pragma unroll
        for (int it = 0; it < 4; it++){
            int idx = it*256 + tid;
            int r = idx >> 3, c8 = idx & 7;
            cpa(&Qs[r*72 + c8*8], &g_qb[((long long)bh*SEQ + qt*128 + r)*DHD + c8*8]);
        }
        CP_COMMIT;
    }

    int r0 = warp*16 + (lane>>2), r1 = r0 + 8;
    float rsq0 = g_rowsumq[bh*SEQ + qt*128 + r0];
    float rsq1 = g_rowsumq[bh*SEQ + qt*128 + r1];

    float m0 = -INFINITY, m1 = -INFINITY;
    float n0 =  INFINITY, n1 =  INFINITY;
    float S0 = 0.f, S1 = 0.f;

    int st = 0;
    for (int kt = 0; kt < 8; kt++){
        bf16*  Kc  = st ? Ks1 : Ks0;
        float* ckc = st ? csk1 : csk0;
        if (kt < 7){
            bf16*  Kn  = st ? Ks0 : Ks1;
            float* ckn = st ? csk0 : csk1;
            #pragma unroll
            for (int it = 0; it < 4; it++){
                int idx = it*256 + tid;
                int r = idx >> 3, c8 = idx & 7;
                cpa(&Kn[r*72 + c8*8], &g_kb[((long long)bh*SEQ + (kt+1)*128 + r)*DHD + c8*8]);
            }
            if (tid < 32) cpa(&ckn[tid*4], &g_colsumk[bh*SEQ + (kt+1)*128 + tid*4]);
            CP_COMMIT;
            CP_WAIT1;
        } else {
            CP_WAIT0;
        }
        __syncthreads();

        float acc[16][4];
        #pragma unroll
        for (int nt = 0; nt < 16; nt++){ acc[nt][0]=0.f; acc[nt][1]=0.f; acc[nt][2]=0.f; acc[nt][3]=0.f; }
        #pragma unroll
        for (int kk = 0; kk < 64; kk += 16){
            u32 af[4];
            ldsm4(af, &Qs[(warp*16 + l16)*72 + kk + (lane>>4)*8]);
            #pragma unroll
            for (int nt = 0; nt < 16; nt++){
                u32 bf[2];
                ldsm2(bf, &Kc[(nt*8 + (l16&7))*72 + kk + ((l16>>3)&1)*8]);
                mma16816(acc[nt], af, bf);
            }
        }

        int c = (lane&3)*2;
        #pragma unroll
        for (int nt = 0; nt < 16; nt++){
            int cg = nt*8 + c;
            float cz0 = ckc[cg]*zq, cz1 = ckc[cg+1]*zq;
            acc[nt][0] = (acc[nt][0] - cz0 - rsq0*zk)*s3;
            acc[nt][1] = (acc[nt][1] - cz1 - rsq0*zk)*s3;
            acc[nt][2] = (acc[nt][2] - cz0 - rsq1*zk)*s3;
            acc[nt][3] = (acc[nt][3] - cz1 - rsq1*zk)*s3;
        }
        float tx0=-INFINITY, tx1=-INFINITY, tn0=INFINITY, tn1=INFINITY;
        #pragma unroll
        for (int nt = 0; nt < 16; nt++){
            tx0 = fmaxf(tx0, fmaxf(acc[nt][0], acc[nt][1]));
            tx1 = fmaxf(tx1, fmaxf(acc[nt][2], acc[nt][3]));
            tn0 = fminf(tn0, fminf(acc[nt][0], acc[nt][1]));
            tn1 = fminf(tn1, fminf(acc[nt][2], acc[nt][3]));
        }
        tx0 = qmax(tx0); tx1 = qmax(tx1);
        tn0 = qmin(tn0); tn1 = qmin(tn1);
        float nm0 = fmaxf(m0, tx0), nm1 = fmaxf(m1, tx1);
        float se0 = 0.f, se1 = 0.f;
        #pragma unroll
        for (int nt = 0; nt < 16; nt++){
            se0 += __expf(acc[nt][0]-nm0) + __expf(acc[nt][1]-nm0);
            se1 += __expf(acc[nt][2]-nm1) + __expf(acc[nt][3]-nm1);
        }
        se0 = qsum(se0); se1 = qsum(se1);
        S0 = S0*__expf(m0-nm0) + se0;  m0 = nm0;  n0 = fminf(n0, tn0);
        S1 = S1*__expf(m1-nm1) + se1;  m1 = nm1;  n1 = fminf(n1, tn1);

        __syncthreads();
        st ^= 1;
    }

    if ((lane & 3) == 0){
        g_rowm[bh*SEQ + qt*128 + r0] = m0;  g_rowS[bh*SEQ + qt*128 + r0] = S0;
        g_rowm[bh*SEQ + qt*128 + r1] = m1;  g_rowS[bh*SEQ + qt*128 + r1] = S1;
    }
    float i0 = __fdiv_rn(1.0f, S0), i1 = __fdiv_rn(1.0f, S1);
    float ax = fmaxf(i0, i1);
    float an = fminf(__expf(n0 - m0)*i0, __expf(n1 - m1)*i1);
    redx[tid] = ax; redn[tid] = an; __syncthreads();
    for (int o = 128; o > 0; o >>= 1){
        if (tid < o){ redx[tid] = fmaxf(redx[tid], redx[tid+o]); redn[tid] = fminf(redn[tid], redn[tid+o]); }
        __syncthreads();
    }
    if (tid == 0){
        atomicMax(&g_stat[10], fenc(redx[0]));
        atomicMin(&g_stat[11], fenc(redn[0]));
    }
}

// ---------------- fused attention: recompute + quantize + AV ----------------
__global__ void __launch_bounds__(256) k_attn_av(){
    extern __shared__ __align__(16) char smraw[];
    bf16* Qs  = (bf16*)smraw;
    bf16* Ks0 = (bf16*)(smraw + 18432);
    bf16* Ks1 = (bf16*)(smraw + 18432*2);
    bf16* Vs  = (bf16*)(smraw + 18432*3);
    float* csk0 = (float*)(smraw + 18432*4);
    float* csk1 = (float*)(smraw + 18432*4 + 512);
    float* vcs  = (float*)(smraw + 18432*4 + 1024);

    int bh = blockIdx.y, qt = blockIdx.x;
    int b = bh / NH, h = bh - b*NH;
    int tid = threadIdx.x, warp = tid >> 5, lane = tid & 31;
    int l16 = lane & 15;

    float sq, zq, iq, sk, zk, ik, sv, zv, iv, sa, za, ia;
    get_szi(2, sq, zq, iq); get_szi(3, sk, zk, ik);
    get_szi(4, sv, zv, iv); get_szi(5, sa, za, ia);
    float s3 = (0.125f * sq) * sk;

    {
        #pragma unroll
        for (int it = 0; it < 4; it++){
            int idx = it*256 + tid;
            int r = idx >> 3, c8 = idx & 7;
            cpa(&Ks0[r*72 + c8*8], &g_kb[((long long)bh*SEQ + r)*DHD + c8*8]);
        }
        if (tid < 32) cpa(&csk0[tid*4], &g_colsumk[bh*SEQ + tid*4]);
        CP_COMMIT;
        #pragma unroll
        for (int it = 0; it < 4; it++){
            int idx = it*256 + tid;
            int r = idx >> 3, c8 = idx & 7;
            cpa(&Qs[r*72 + c8*8], &g_qb[((long long)bh*SEQ + qt*128 + r)*DHD + c8*8]);
        }
        if (tid < 16) cpa(&vcs[tid*4], &g_vcolsum[bh*DHD + tid*4]);
        CP_COMMIT;
    }

    int r0 = warp*16 + (lane>>2), r1 = r0 + 8;
    float rsq0 = g_rowsumq[bh*SEQ + qt*128 + r0];
    float rsq1 = g_rowsumq[bh*SEQ + qt*128 + r1];
    float m0 = g_rowm[bh*SEQ + qt*128 + r0], S0 = g_rowS[bh*SEQ + qt*128 + r0];
    float m1 = g_rowm[bh*SEQ + qt*128 + r1], S1 = g_rowS[bh*SEQ + qt*128 + r1];
    // q = rint(e * coef + za), coef = (1/S)*(1/sa)
    float coef0 = __fdiv_rn(1.0f, S0) * ia;
    float coef1 = __fdiv_rn(1.0f, S1) * ia;

    float oacc[8][4];
    #pragma unroll
    for (int nt = 0; nt < 8; nt++){ oacc[nt][0]=0.f; oacc[nt][1]=0.f; oacc[nt][2]=0.f; oacc[nt][3]=0.f; }
    float aqs0 = 0.f, aqs1 = 0.f;

    int st = 0;
    for (int kt = 0; kt < 8; kt++){
        bf16*  Kc  = st ? Ks1 : Ks0;
        float* ckc = st ? csk1 : csk0;
        if (kt < 7){
            bf16*  Kn  = st ? Ks0 : Ks1;
            float* ckn = st ? csk0 : csk1;
            #pragma unroll
            for (int it = 0; it < 4; it++){
                int idx = it*256 + tid;
                int r = idx >> 3, c8 = idx & 7;
                cpa(&Kn[r*72 + c8*8], &g_kb[((long long)bh*SEQ + (kt+1)*128 + r)*DHD + c8*8]);
            }
            if (tid < 32) cpa(&ckn[tid*4], &g_colsumk[bh*SEQ + (kt+1)*128 + tid*4]);
            CP_COMMIT;
        }
        #pragma unroll
        for (int it = 0; it < 4; it++){
            int idx = it*256 + tid;
            int r = idx >> 3, c8 = idx & 7;
            cpa(&Vs[r*72 + c8*8], &g_vb[((long long)bh*SEQ + kt*128 + r)*DHD + c8*8]);
        }
        CP_COMMIT;
        if (kt < 7) { CP_WAIT2; } else { CP_WAIT1; }
        __syncthreads();

        float acc[16][4];
        #pragma unroll
        for (int nt = 0; nt < 16; nt++){ acc[nt][0]=0.f; acc[nt][1]=0.f; acc[nt][2]=0.f; acc[nt][3]=0.f; }
        #pragma unroll
        for (int kk = 0; kk < 64; kk += 16){
            u32 af[4];
            ldsm4(af, &Qs[(warp*16 + l16)*72 + kk + (lane>>4)*8]);
            #pragma unroll
            for (int nt = 0; nt < 16; nt++){
                u32 bf[2];
                ldsm2(bf, &Kc[(nt*8 + (l16&7))*72 + kk + ((l16>>3)&1)*8]);
                mma16816(acc[nt], af, bf);
            }
        }

        int c = (lane&3)*2;
        #pragma unroll
        for (int nt = 0; nt < 16; nt++){
            int cg = nt*8 + c;
            float cz0 = ckc[cg]*zq, cz1 = ckc[cg+1]*zq;
            acc[nt][0] = (acc[nt][0] - cz0 - rsq0*zk)*s3;
            acc[nt][1] = (acc[nt][1] - cz1 - rsq0*zk)*s3;
            acc[nt][2] = (acc[nt][2] - cz0 - rsq1*zk)*s3;
            acc[nt][3] = (acc[nt][3] - cz1 - rsq1*zk)*s3;
        }

        if (kt < 7) { CP_WAIT1; } else { CP_WAIT0; }
        __syncthreads();

        #pragma unroll
        for (int j = 0; j < 8; j++){
            float q00 = rintf(fmaf(__expf(acc[2*j][0]   - m0), coef0, za));
            float q01 = rintf(fmaf(__expf(acc[2*j][1]   - m0), coef0, za));
            float q02 = rintf(fmaf(__expf(acc[2*j][2]   - m1), coef1, za));
            float q03 = rintf(fmaf(__expf(acc[2*j][3]   - m1), coef1, za));
            float q10 = rintf(fmaf(__expf(acc[2*j+1][0] - m0), coef0, za));
            float q11 = rintf(fmaf(__expf(acc[2*j+1][1] - m0), coef0, za));
            float q12 = rintf(fmaf(__expf(acc[2*j+1][2] - m1), coef1, za));
            float q13 = rintf(fmaf(__expf(acc[2*j+1][3] - m1), coef1, za));
            aqs0 += q00 + q01 + q10 + q11;
            aqs1 += q02 + q03 + q12 + q13;
            u32 pa[4];
            pa[0] = packbf2(q00, q01);
            pa[1] = packbf2(q02, q03);
            pa[2] = packbf2(q10, q11);
            pa[3] = packbf2(q12, q13);
            #pragma unroll
            for (int nt = 0; nt < 8; nt++){
                u32 vf[2];
                ldsm2t(vf, &Vs[(16*j + l16)*72 + nt*8]);
                mma16816(oacc[nt], pa, vf);
            }
        }
        __syncthreads();
        st ^= 1;
    }

    aqs0 = qsum(aqs0);
    aqs1 = qsum(aqs1);

    float mult  = sa * sv;
    float cterm = (za * zv) * (float)SEQ;
    int c = (lane&3)*2;
    long long ob0 = (long long)(b*SEQ + qt*128 + r0)*DMODEL + h*DHD;
    long long ob1 = (long long)(b*SEQ + qt*128 + r1)*DMODEL + h*DHD;
    #pragma unroll
    for (int nt = 0; nt < 8; nt++){
        int d0 = nt*8 + c;
        float w0 = vcs[d0]*za, w1 = vcs[d0+1]*za;
        g_outbuf[ob0 + d0]     = (oacc[nt][0] - w0 - aqs0*zv + cterm)*mult;
        g_outbuf[ob0 + d0 + 1] = (oacc[nt][1] - w1 - aqs0*zv + cterm)*mult;
        g_outbuf[ob1 + d0]     = (oacc[nt][2] - w0 - aqs1*zv + cterm)*mult;
        g_outbuf[ob1 + d0 + 1] = (oacc[nt][3] - w1 - aqs1*zv + cterm)*mult;
    }
}

// ---------------- pipelined tensor-core GEMM with affine epilogue ----------------
template<int F1>
__global__ void __launch_bounds__(256) k_mma(
    const bf16* __restrict__ A, int lda,
    const bf16* __restrict__ Bm, int ldb,
    float* __restrict__ C, int ldc,
    int K,
    const float* __restrict__ colsumB,
    const float* __restrict__ rowsumA,
    int slotA, int slotB, float Kconst,
    const float* __restrict__ bias)
{
    const int BK = 32, APAD = 40, BPAD = 136;
    __shared__ __align__(16) bf16 As[2][128*APAD];
    __shared__ __align__(16) bf16 Bs[2][BK*BPAD];
    __shared__ float redx[256], redn[256];

    int i0 = blockIdx.y * 128, j0 = blockIdx.x * 128;
    int tid = threadIdx.x, warp = tid >> 5, lane = tid & 31;
    int wm = warp >> 2, wn = warp & 3;
    int l16 = lane & 15;

    float acc[4][4][4];
    #pragma unroll
    for (int a = 0; a < 4; a++)
        #pragma unroll
        for (int b = 0; b < 4; b++){
            acc[a][b][0]=0.f; acc[a][b][1]=0.f; acc[a][b][2]=0.f; acc[a][b][3]=0.f;
        }

    {
        #pragma unroll
        for (int v = 0; v < 2; v++){
            int idx = v*256 + tid;
            int r = idx >> 2, c8 = idx & 3;
            cpa(&As[0][r*APAD + c8*8], &A[(long long)(i0 + r)*lda + c8*8]);
        }
        #pragma unroll
        for (int v = 0; v < 2; v++){
            int idx = v*256 + tid;
            int r = idx >> 4, c8 = idx & 15;
            cpa(&Bs[0][r*BPAD + c8*8], &Bm[(long long)r*ldb + j0 + c8*8]);
        }
        CP_COMMIT;
    }

    int st = 0;
    for (int k0 = 0; k0 < K; k0 += BK){
        if (k0 + BK < K){
            int ns = st ^ 1, kn = k0 + BK;
            #pragma unroll
            for (int v = 0; v < 2; v++){
                int idx = v*256 + tid;
                int r = idx >> 2, c8 = idx & 3;
                cpa(&As[ns][r*APAD + c8*8], &A[(long long)(i0 + r)*lda + kn + c8*8]);
            }
            #pragma unroll
            for (int v = 0; v < 2; v++){
                int idx = v*256 + tid;
                int r = idx >> 4, c8 = idx & 15;
                cpa(&Bs[ns][r*BPAD + c8*8], &Bm[(long long)(kn + r)*ldb + j0 + c8*8]);
            }
            CP_COMMIT;
            CP_WAIT1;
        } else {
            CP_WAIT0;
        }
        __syncthreads();

        #pragma unroll
        for (int kk = 0; kk < BK; kk += 16){
            u32 af[4][4];
            #pragma unroll
            for (int mt = 0; mt < 4; mt++)
                ldsm4(af[mt], &As[st][(wm*64 + mt*16 + l16)*APAD + kk + (lane>>4)*8]);
            u32 bf[4][2];
            #pragma unroll
            for (int nt = 0; nt < 4; nt++)
                ldsm2t(bf[nt], &Bs[st][(kk + l16)*BPAD + wn*32 + nt*8]);
            #pragma unroll
            for (int mt = 0; mt < 4; mt++)
                #pragma unroll
                for (int nt = 0; nt < 4; nt++)
                    mma16816(acc[mt][nt], af[mt], bf[nt]);
        }
        __syncthreads();
        st ^= 1;
    }

    float sA, zA, iA, sB, zB, iB;
    get_szi(slotA, sA, zA, iA); get_szi(slotB, sB, zB, iB);
    float mult  = sA * sB;
    float cterm = (zA * zB) * Kconst;

    float lmx = -INFINITY, lmn = INFINITY;

    #pragma unroll
    for (int mt = 0; mt < 4; mt++){
        int row0 = i0 + wm*64 + mt*16 + (lane>>2);
        float rs0 = rowsumA[row0], rs1 = rowsumA[row0+8];
        float p0 = 0.f, p8 = 0.f;
        #pragma unroll
        for (int nt = 0; nt < 4; nt++){
            int col0 = j0 + wn*32 + nt*8 + (lane&3)*2;
            float cs0 = colsumB[col0], cs1 = colsumB[col0+1];
            float b0 = bias ? bias[col0]   : 0.f;
            float b1 = bias ? bias[col0+1] : 0.f;
            float v0 = (acc[mt][nt][0] - cs0*zA - rs0*zB + cterm)*mult + b0;
            float v1 = (acc[mt][nt][1] - cs1*zA - rs0*zB + cterm)*mult + b1;
            float v2 = (acc[mt][nt][2] - cs0*zA - rs1*zB + cterm)*mult + b0;
            float v3 = (acc[mt][nt][3] - cs1*zA - rs1*zB + cterm)*mult + b1;
            C[(long long)row0*ldc + col0]       = v0;
            C[(long long)row0*ldc + col0 + 1]   = v1;
            C[(long long)(row0+8)*ldc + col0]   = v2;
            C[(long long)(row0+8)*ldc + col0+1] = v3;
            if (F1){
                p0 += v0 + v1; p8 += v2 + v3;
                lmx = fmaxf(lmx, fmaxf(fmaxf(v0,v1), fmaxf(v2,v3)));
                lmn = fminf(lmn, fminf(fminf(v0,v1), fminf(v2,v3)));
            }
        }
        if (F1){
            p0 = qsum(p0); p8 = qsum(p8);
            if ((lane & 3) == 0){
                atomicAdd(&g_xqkvsum[row0],   p0);
                atomicAdd(&g_xqkvsum[row0+8], p8);
            }
        }
    }

    if (F1){
        redx[tid] = lmx; redn[tid] = lmn; __syncthreads();
        for (int o = 128; o > 0; o >>= 1){
            if (tid < o){ redx[tid] = fmaxf(redx[tid], redx[tid+o]); redn[tid] = fminf(redn[tid], redn[tid+o]); }
            __syncthreads();
        }
        if (tid == 0){
            int region = blockIdx.x / 6;
            atomicMax(&g_stat[2*(2+region)],   fenc(redx[0]));
            atomicMin(&g_stat[2*(2+region)+1], fenc(redn[0]));
        }
    }
}

// ---------------- launcher ----------------
extern "C" void kernel_launch(void* const* d_in, const int* in_sizes, int n_in,
                              void* d_out, int out_size){
    const float *x = 0, *wqkv = 0, *wout = 0, *bout = 0;
    for (int i = 0; i < n_in; i++){
        if      (in_sizes[i] == MROWS*DMODEL)  x    = (const float*)d_in[i];
        else if (in_sizes[i] == J3*DMODEL)     wqkv = (const float*)d_in[i];
        else if (in_sizes[i] == DMODEL*DMODEL) wout = (const float*)d_in[i];
        else if (in_sizes[i] == DMODEL)        bout = (const float*)d_in[i];
    }
    float* out = (float*)d_out;

    bf16 *p_xq, *p_wq1, *p_wq2;
    float *p_xqkv, *p_outbuf;
    float *p_rowsum_x, *p_colsum_w1, *p_colsum_w2, *p_xqkvsum;
    cudaGetSymbolAddress((void**)&p_xq,        g_xq);
    cudaGetSymbolAddress((void**)&p_wq1,       g_wq1);
    cudaGetSymbolAddress((void**)&p_wq2,       g_wq2);
    cudaGetSymbolAddress((void**)&p_xqkv,      g_xqkv);
    cudaGetSymbolAddress((void**)&p_outbuf,    g_outbuf);
    cudaGetSymbolAddress((void**)&p_rowsum_x,  g_rowsum_x);
    cudaGetSymbolAddress((void**)&p_colsum_w1, g_colsum_w1);
    cudaGetSymbolAddress((void**)&p_colsum_w2, g_colsum_w2);
    cudaGetSymbolAddress((void**)&p_xqkvsum,   g_xqkvsum);

    static int smem_set = 0;
    if (!smem_set){
        cudaFuncSetAttribute(k_attn_stats, cudaFuncAttributeMaxDynamicSharedMemorySize, 18432*3 + 2048);
        cudaFuncSetAttribute(k_attn_av,    cudaFuncAttributeMaxDynamicSharedMemorySize, 18432*4 + 2048);
        smem_set = 1;
    }

    k_init<<<1, 256>>>();
    k_minmax2<<<dim3(768, 2), 256>>>(x, MROWS*DMODEL, 0, wqkv, J3*DMODEL, 1);
    k_quantrow<<<MROWS/8, 256>>>(x, p_xq, p_rowsum_x, 0);
    k_quantW<<<dim3(J3/32, DMODEL/32), 256>>>(wqkv, p_wq1, p_colsum_w1, 1, DMODEL, J3);
    k_mma<1><<<dim3(J3/128, MROWS/128), 256>>>(
        p_xq, DMODEL, p_wq1, J3, p_xqkv, J3, DMODEL,
        p_colsum_w1, p_rowsum_x, 0, 1, (float)DMODEL, (const float*)0);
    k_pack_qkv<<<dim3(SEQ/8, BHN), 256>>>();
    k_attn_stats<<<dim3(8, BHN), 256, 18432*3 + 2048>>>();
    k_attn_av<<<dim3(8, BHN), 256, 18432*4 + 2048>>>();
    k_minmax2<<<dim3(768, 2), 256>>>(p_outbuf, MROWS*DMODEL, 6, wout, DMODEL*DMODEL, 7);
    k_quantrow<<<MROWS/8, 256>>>(p_outbuf, p_xq, p_rowsum_x /*dummy*/, 6);
    k_quantW<<<dim3(DMODEL/32, DMODEL/32), 256>>>(wout, p_wq2, p_colsum_w2, 7, DMODEL, DMODEL);
    k_mma<0><<<dim3(DMODEL/128, MROWS/128), 256>>>(
        p_xq, DMODEL, p_wq2, DMODEL, out, DMODEL, DMODEL,
        p_colsum_w2, p_xqkvsum, 6, 7, (float)J3, bout);
}